// round 1
// baseline (speedup 1.0000x reference)
#include <cuda_runtime.h>
#include <math.h>

// Problem constants
#define BATCH   2
#define S_LEN   2048
#define HIDDEN  2048
#define NH      16
#define NKV     2
#define HD      128
#define REP     (NH / NKV)          // 8
#define QKV_COLS ((NH + 2 * NKV) * HD)  // 2560
#define ROWS    (BATCH * S_LEN)     // 4096
#define SCALE_F   0.08838834764831845f
#define SOFTCAP_F 30.0f

// Scratch (allocation-free rule: __device__ globals)
static __device__ float g_qkv[(size_t)ROWS * QKV_COLS];   // ~41.9 MB
static __device__ float g_attn[(size_t)ROWS * HIDDEN];    // ~33.5 MB
static __device__ float g_cos[S_LEN * (HD / 2)];
static __device__ float g_sin[S_LEN * (HD / 2)];

// ---------------------------------------------------------------------------
// RoPE table: computed in double so it's accurate even under --use_fast_math
// (angles reach ~2047 rad; fast sinf would be wildly wrong there).
// ---------------------------------------------------------------------------
__global__ void rope_table_kernel() {
    int i = blockIdx.x * blockDim.x + threadIdx.x;
    if (i >= S_LEN * 64) return;
    int s = i >> 6;
    int d = i & 63;
    double inv_freq = pow(10000.0, -(double)d / 64.0);
    double a = (double)s * inv_freq;
    g_cos[i] = (float)cos(a);
    g_sin[i] = (float)sin(a);
}

// ---------------------------------------------------------------------------
// RoPE apply (in-place on qkv scratch). heads 0..15 = Q, 16..17 = K.
// ---------------------------------------------------------------------------
__global__ void rope_apply_kernel(float* __restrict__ qkv) {
    int i = blockIdx.x * blockDim.x + threadIdx.x;
    const int total = ROWS * 18 * 64;
    if (i >= total) return;
    int d    = i & 63;
    int rest = i >> 6;
    int hh   = rest % 18;
    int row  = rest / 18;          // b*S + s
    int s    = row & (S_LEN - 1);
    size_t base = (size_t)row * QKV_COLS +
                  (hh < 16 ? (size_t)hh * HD : (size_t)(NH * HD) + (size_t)(hh - 16) * HD);
    float c  = g_cos[(s << 6) + d];
    float sn = g_sin[(s << 6) + d];
    float x1 = qkv[base + d];
    float x2 = qkv[base + d + 64];
    qkv[base + d]      = x1 * c - x2 * sn;
    qkv[base + d + 64] = x1 * sn + x2 * c;
}

// ---------------------------------------------------------------------------
// SGEMM: C[M,N] = A[M,K] @ B[K,N], row-major, fp32 FMA.
// 128x128 block, BK=8, 8x8 per-thread micro-tile, 256 threads, vectorized.
// All dims here are multiples of 128/8, so no bounds checks.
// ---------------------------------------------------------------------------
__global__ __launch_bounds__(256, 2)
void sgemm_kernel(const float* __restrict__ A, const float* __restrict__ B,
                  float* __restrict__ C, int M, int N, int K) {
    constexpr int BM = 128, BN = 128, BK = 8, TM = 8, TN = 8;
    __shared__ float As[BK][BM];
    __shared__ float Bs[BK][BN];

    const int tid  = threadIdx.x;
    const int brow = blockIdx.y, bcol = blockIdx.x;

    const float* Ab = A + (size_t)brow * BM * K;
    const float* Bb = B + (size_t)bcol * BN;
    float*       Cb = C + (size_t)brow * BM * N + (size_t)bcol * BN;

    const int trow = (tid / 16) * TM;
    const int tcol = (tid % 16) * TN;
    const int aRow = tid >> 1;
    const int aCol = (tid & 1) * 4;
    const int bRow = tid >> 5;
    const int bCol = (tid & 31) * 4;

    float acc[TM][TN];
#pragma unroll
    for (int i = 0; i < TM; i++)
#pragma unroll
        for (int j = 0; j < TN; j++) acc[i][j] = 0.0f;

    for (int k0 = 0; k0 < K; k0 += BK) {
        float4 a4 = *(const float4*)(Ab + (size_t)aRow * K + k0 + aCol);
        As[aCol + 0][aRow] = a4.x;
        As[aCol + 1][aRow] = a4.y;
        As[aCol + 2][aRow] = a4.z;
        As[aCol + 3][aRow] = a4.w;
        *(float4*)(&Bs[bRow][bCol]) = *(const float4*)(Bb + (size_t)(k0 + bRow) * N + bCol);
        __syncthreads();

#pragma unroll
        for (int k = 0; k < BK; k++) {
            float ra[TM], rb[TN];
#pragma unroll
            for (int i = 0; i < TM; i++) ra[i] = As[k][trow + i];
#pragma unroll
            for (int j = 0; j < TN; j++) rb[j] = Bs[k][tcol + j];
#pragma unroll
            for (int i = 0; i < TM; i++)
#pragma unroll
                for (int j = 0; j < TN; j++) acc[i][j] += ra[i] * rb[j];
        }
        __syncthreads();
    }

#pragma unroll
    for (int i = 0; i < TM; i++) {
#pragma unroll
        for (int j = 0; j < TN; j += 4) {
            *(float4*)(Cb + (size_t)(trow + i) * N + tcol + j) =
                make_float4(acc[i][j], acc[i][j + 1], acc[i][j + 2], acc[i][j + 3]);
        }
    }
}

// ---------------------------------------------------------------------------
// Flash attention, fp32: per block = one (batch, head, 64-row Q tile).
// Online softmax with softcap: p = exp(30*tanh(s*SCALE/30) - m).
// 256 threads as 16x16: each thread owns 4 Q rows; S micro-tile 4x4,
// O micro-tile 4x8 (same rows). Row reductions via shuffle across the 16
// tx lanes. Smem: Q[64][128] + Kt[128][64] + V[64][128] + P[64][64] = 112 KB.
// ---------------------------------------------------------------------------
#define ATTN_SMEM_FLOATS (64 * 128 * 3 + 64 * 64)
#define ATTN_SMEM_BYTES  (ATTN_SMEM_FLOATS * 4)

__global__ __launch_bounds__(256, 1)
void attn_kernel(const float* __restrict__ qkv, float* __restrict__ out) {
    constexpr int BM = 64, BN = 64;
    extern __shared__ float sm[];
    float* Qs = sm;                   // [64][128]
    float* Kt = Qs + 64 * 128;        // [128][64]  (transposed K)
    float* Vs = Kt + 128 * 64;        // [64][128]
    float* Ps = Vs + 64 * 128;        // [64][64]

    const int qb = blockIdx.x;        // q tile (0..31)
    const int h  = blockIdx.y;        // q head
    const int b  = blockIdx.z;        // batch
    const int g  = h / REP;           // kv head

    const int tid = threadIdx.x;
    const int ty  = tid / 16;         // 0..15 -> rows ty*4..ty*4+3
    const int tx  = tid % 16;         // 0..15

    const size_t rs = QKV_COLS;
    const float* qbase = qkv + ((size_t)b * S_LEN + (size_t)qb * BM) * rs + (size_t)h * HD;
    const float* kbase = qkv + (size_t)b * S_LEN * rs + (size_t)(NH * HD) + (size_t)g * HD;
    const float* vbase = kbase + (size_t)(NKV * HD);

    // load Q tile (each thread: 8 float4)
    for (int idx = tid; idx < 64 * 32; idx += 256) {
        int r = idx >> 5, c4 = idx & 31;
        *(float4*)&Qs[r * 128 + c4 * 4] = *(const float4*)(qbase + (size_t)r * rs + c4 * 4);
    }

    float m[4], l[4], o[4][8];
#pragma unroll
    for (int i = 0; i < 4; i++) {
        m[i] = -1e30f;
        l[i] = 0.0f;
#pragma unroll
        for (int j = 0; j < 8; j++) o[i][j] = 0.0f;
    }

    for (int kt = 0; kt <= qb; kt++) {
        const float* kb = kbase + (size_t)kt * BN * rs;
        const float* vb = vbase + (size_t)kt * BN * rs;
        // load K (transposed into Kt) and V
        for (int idx = tid; idx < 64 * 32; idx += 256) {
            int r = idx >> 5, c4 = idx & 31;
            float4 kv4 = *(const float4*)(kb + (size_t)r * rs + c4 * 4);
            Kt[(c4 * 4 + 0) * BN + r] = kv4.x;
            Kt[(c4 * 4 + 1) * BN + r] = kv4.y;
            Kt[(c4 * 4 + 2) * BN + r] = kv4.z;
            Kt[(c4 * 4 + 3) * BN + r] = kv4.w;
            *(float4*)&Vs[r * 128 + c4 * 4] = *(const float4*)(vb + (size_t)r * rs + c4 * 4);
        }
        __syncthreads();

        // S = Q K^T  (4x4 per thread)
        float s[4][4];
#pragma unroll
        for (int i = 0; i < 4; i++)
#pragma unroll
            for (int j = 0; j < 4; j++) s[i][j] = 0.0f;

        for (int d = 0; d < 128; d += 4) {
            float kv[4][4];
#pragma unroll
            for (int q = 0; q < 4; q++) {
                float4 t = *(float4*)&Kt[(d + q) * BN + tx * 4];
                kv[q][0] = t.x; kv[q][1] = t.y; kv[q][2] = t.z; kv[q][3] = t.w;
            }
#pragma unroll
            for (int i = 0; i < 4; i++) {
                float4 t = *(float4*)&Qs[(ty * 4 + i) * 128 + d];
                float qv[4] = {t.x, t.y, t.z, t.w};
#pragma unroll
                for (int q = 0; q < 4; q++)
#pragma unroll
                    for (int j = 0; j < 4; j++) s[i][j] += qv[q] * kv[q][j];
            }
        }

        // softcap + causal mask + online softmax update
        const bool diag = (kt == qb);
        float mnew[4];
#pragma unroll
        for (int i = 0; i < 4; i++) {
            int rloc = ty * 4 + i;
            float mx = -1e30f;
#pragma unroll
            for (int j = 0; j < 4; j++) {
                float v = SOFTCAP_F * tanhf(s[i][j] * (SCALE_F / SOFTCAP_F));
                if (diag && (tx * 4 + j) > rloc) v = -1e30f;
                s[i][j] = v;
                mx = fmaxf(mx, v);
            }
#pragma unroll
            for (int off = 1; off < 16; off <<= 1)
                mx = fmaxf(mx, __shfl_xor_sync(0xffffffffu, mx, off));
            mnew[i] = fmaxf(m[i], mx);
        }

#pragma unroll
        for (int i = 0; i < 4; i++) {
            float corr = expf(m[i] - mnew[i]);   // first iter: exp(-1e30)=0
            l[i] *= corr;
#pragma unroll
            for (int j = 0; j < 8; j++) o[i][j] *= corr;
            float sum = 0.0f;
#pragma unroll
            for (int j = 0; j < 4; j++) {
                float p = expf(s[i][j] - mnew[i]);  // masked -> exp(-1e30)=0
                Ps[(ty * 4 + i) * BN + tx * 4 + j] = p;
                sum += p;
            }
#pragma unroll
            for (int off = 1; off < 16; off <<= 1)
                sum += __shfl_xor_sync(0xffffffffu, sum, off);
            l[i] += sum;
            m[i] = mnew[i];
        }
        __syncthreads();

        // O += P @ V  (4 rows x 8 cols per thread)
        for (int kk = 0; kk < BN; kk++) {
            float4 v0 = *(float4*)&Vs[kk * 128 + tx * 8];
            float4 v1 = *(float4*)&Vs[kk * 128 + tx * 8 + 4];
#pragma unroll
            for (int i = 0; i < 4; i++) {
                float p = Ps[(ty * 4 + i) * BN + kk];
                o[i][0] += p * v0.x; o[i][1] += p * v0.y;
                o[i][2] += p * v0.z; o[i][3] += p * v0.w;
                o[i][4] += p * v1.x; o[i][5] += p * v1.y;
                o[i][6] += p * v1.z; o[i][7] += p * v1.w;
            }
        }
        __syncthreads();  // before next tile's K/V overwrite
    }

    // normalize and write out[b*S+row][h*128 + col]
#pragma unroll
    for (int i = 0; i < 4; i++) {
        float inv = 1.0f / l[i];
        int row = qb * BM + ty * 4 + i;
        float* op = out + ((size_t)b * S_LEN + row) * (size_t)HIDDEN + (size_t)h * HD + tx * 8;
        *(float4*)(op)     = make_float4(o[i][0] * inv, o[i][1] * inv, o[i][2] * inv, o[i][3] * inv);
        *(float4*)(op + 4) = make_float4(o[i][4] * inv, o[i][5] * inv, o[i][6] * inv, o[i][7] * inv);
    }
}

// ---------------------------------------------------------------------------
// Launch
// ---------------------------------------------------------------------------
extern "C" void kernel_launch(void* const* d_in, const int* in_sizes, int n_in,
                              void* d_out, int out_size) {
    (void)in_sizes; (void)n_in; (void)out_size;
    const float* hidden = (const float*)d_in[0];
    const float* Wqkv   = (const float*)d_in[1];
    const float* Wo     = (const float*)d_in[2];
    float* out = (float*)d_out;

    void* p;
    cudaGetSymbolAddress(&p, g_qkv);  float* qkv  = (float*)p;
    cudaGetSymbolAddress(&p, g_attn); float* attn = (float*)p;

    cudaFuncSetAttribute(attn_kernel, cudaFuncAttributeMaxDynamicSharedMemorySize,
                         ATTN_SMEM_BYTES);

    // RoPE tables (independent of GEMM; same stream, ordered)
    rope_table_kernel<<<(S_LEN * 64 + 255) / 256, 256>>>();

    // 1) QKV projection: [4096,2048] @ [2048,2560]
    sgemm_kernel<<<dim3(QKV_COLS / 128, ROWS / 128), 256>>>(hidden, Wqkv, qkv,
                                                            ROWS, QKV_COLS, HIDDEN);
    // 2) RoPE on Q (16 heads) + K (2 heads), in place
    {
        int total = ROWS * 18 * 64;
        rope_apply_kernel<<<(total + 255) / 256, 256>>>(qkv);
    }
    // 3) Flash attention with softcap + causal + GQA
    attn_kernel<<<dim3(S_LEN / 64, NH, BATCH), 256, ATTN_SMEM_BYTES>>>(qkv, attn);

    // 4) Output projection: [4096,2048] @ [2048,2048]
    sgemm_kernel<<<dim3(HIDDEN / 128, ROWS / 128), 256>>>(attn, Wo, out,
                                                          ROWS, HIDDEN, HIDDEN);
}

// round 2
// speedup vs baseline: 2.9055x; 2.9055x over previous
#include <cuda_runtime.h>
#include <math.h>
#include <stdint.h>

// Problem constants
#define BATCH   2
#define S_LEN   2048
#define HIDDEN  2048
#define NH      16
#define NKV     2
#define HD      128
#define REP     (NH / NKV)              // 8
#define QKV_COLS ((NH + 2 * NKV) * HD)  // 2560
#define ROWS    (BATCH * S_LEN)         // 4096
#define SCALE_F   0.08838834764831845f
#define SOFTCAP_F 30.0f

// Scratch (allocation-free rule: __device__ globals)
static __device__ float g_qkv[(size_t)ROWS * QKV_COLS];   // ~41.9 MB
static __device__ float g_attn[(size_t)ROWS * HIDDEN];    // ~33.5 MB
static __device__ float g_cos[S_LEN * (HD / 2)];
static __device__ float g_sin[S_LEN * (HD / 2)];

// ---------------------------------------------------------------------------
// Helpers: tf32 conversion + mma.sync
// ---------------------------------------------------------------------------
__device__ __forceinline__ float f2tf32(float x) {
    uint32_t u;
    asm("cvt.rna.tf32.f32 %0, %1;" : "=r"(u) : "f"(x));
    return __uint_as_float(u);
}

// D(16x8,f32) += A(16x8,tf32,row) * B(8x8,tf32,col)
__device__ __forceinline__ void mma_tf32(float* d, const uint32_t* a, const uint32_t* b) {
    asm volatile(
        "mma.sync.aligned.m16n8k8.row.col.f32.tf32.tf32.f32 "
        "{%0,%1,%2,%3}, {%4,%5,%6,%7}, {%8,%9}, {%0,%1,%2,%3};\n"
        : "+f"(d[0]), "+f"(d[1]), "+f"(d[2]), "+f"(d[3])
        : "r"(a[0]), "r"(a[1]), "r"(a[2]), "r"(a[3]), "r"(b[0]), "r"(b[1]));
}

// ---------------------------------------------------------------------------
// RoPE table in double precision (safe under fast-math; angles up to ~2047 rad)
// ---------------------------------------------------------------------------
__global__ void rope_table_kernel() {
    int i = blockIdx.x * blockDim.x + threadIdx.x;
    if (i >= S_LEN * 64) return;
    int s = i >> 6;
    int d = i & 63;
    double inv_freq = pow(10000.0, -(double)d / 64.0);
    double a = (double)s * inv_freq;
    g_cos[i] = (float)cos(a);
    g_sin[i] = (float)sin(a);
}

__global__ void rope_apply_kernel(float* __restrict__ qkv) {
    int i = blockIdx.x * blockDim.x + threadIdx.x;
    const int total = ROWS * 18 * 64;
    if (i >= total) return;
    int d    = i & 63;
    int rest = i >> 6;
    int hh   = rest % 18;
    int row  = rest / 18;
    int s    = row & (S_LEN - 1);
    size_t base = (size_t)row * QKV_COLS +
                  (hh < 16 ? (size_t)hh * HD : (size_t)(NH * HD) + (size_t)(hh - 16) * HD);
    float c  = g_cos[(s << 6) + d];
    float sn = g_sin[(s << 6) + d];
    float x1 = qkv[base + d];
    float x2 = qkv[base + d + 64];
    qkv[base + d]      = x1 * c - x2 * sn;
    qkv[base + d + 64] = x1 * sn + x2 * c;
}

// ---------------------------------------------------------------------------
// TF32 tensor-core GEMM: C[M,N] = A[M,K] @ B[K,N], row-major.
// BM=BN=128, BK=16, 256 threads = 8 warps in 4x2 grid, warp tile 32x64.
// Padded smem strides (20 / 132) make every mma-fragment LDS conflict-free.
// M%128==0, N%128==0, K%16==0 guaranteed by problem sizes.
// ---------------------------------------------------------------------------
__global__ __launch_bounds__(256, 2)
void gemm_tf32(const float* __restrict__ A, const float* __restrict__ B,
               float* __restrict__ C, int M, int N, int K) {
    constexpr int BM = 128, BN = 128, BK = 16;
    __shared__ float As[BM][20];   // [row][k]   stride 20 -> conflict-free frags
    __shared__ float Bs[BK][132];  // [k][col]   stride 132 -> conflict-free frags

    const int tid  = threadIdx.x;
    const int lane = tid & 31;
    const int warp = tid >> 5;
    const int wm = warp >> 1;          // 0..3
    const int wn = warp & 1;           // 0..1
    const int g4  = lane >> 2;         // groupID 0..7
    const int t4  = lane & 3;          // threadInGroup 0..3

    const float* Ab = A + (size_t)blockIdx.y * BM * K;
    const float* Bb = B + (size_t)blockIdx.x * BN;

    const int aRow = tid >> 2;             // 0..63 (+64)
    const int aCol = (tid & 3) * 4;        // 0,4,8,12
    const int bRow = tid >> 5;             // 0..7 (+8)
    const int bCol = (tid & 31) * 4;       // 0..124

    float acc[2][8][4];
#pragma unroll
    for (int mt = 0; mt < 2; mt++)
#pragma unroll
        for (int nt = 0; nt < 8; nt++)
#pragma unroll
            for (int r = 0; r < 4; r++) acc[mt][nt][r] = 0.0f;

    for (int k0 = 0; k0 < K; k0 += BK) {
        // load A tile (2 float4 per thread), convert to tf32
        {
            float4 v = *(const float4*)(Ab + (size_t)aRow * K + k0 + aCol);
            As[aRow][aCol + 0] = f2tf32(v.x); As[aRow][aCol + 1] = f2tf32(v.y);
            As[aRow][aCol + 2] = f2tf32(v.z); As[aRow][aCol + 3] = f2tf32(v.w);
            v = *(const float4*)(Ab + (size_t)(aRow + 64) * K + k0 + aCol);
            As[aRow + 64][aCol + 0] = f2tf32(v.x); As[aRow + 64][aCol + 1] = f2tf32(v.y);
            As[aRow + 64][aCol + 2] = f2tf32(v.z); As[aRow + 64][aCol + 3] = f2tf32(v.w);
        }
        // load B tile (2 float4 per thread), convert to tf32
        {
            float4 v = *(const float4*)(Bb + (size_t)(k0 + bRow) * N + bCol);
            Bs[bRow][bCol + 0] = f2tf32(v.x); Bs[bRow][bCol + 1] = f2tf32(v.y);
            Bs[bRow][bCol + 2] = f2tf32(v.z); Bs[bRow][bCol + 3] = f2tf32(v.w);
            v = *(const float4*)(Bb + (size_t)(k0 + bRow + 8) * N + bCol);
            Bs[bRow + 8][bCol + 0] = f2tf32(v.x); Bs[bRow + 8][bCol + 1] = f2tf32(v.y);
            Bs[bRow + 8][bCol + 2] = f2tf32(v.z); Bs[bRow + 8][bCol + 3] = f2tf32(v.w);
        }
        __syncthreads();

#pragma unroll
        for (int ks = 0; ks < BK; ks += 8) {
            uint32_t af[2][4];
#pragma unroll
            for (int mt = 0; mt < 2; mt++) {
                int r = wm * 32 + mt * 16 + g4;
                af[mt][0] = __float_as_uint(As[r][ks + t4]);
                af[mt][1] = __float_as_uint(As[r + 8][ks + t4]);
                af[mt][2] = __float_as_uint(As[r][ks + t4 + 4]);
                af[mt][3] = __float_as_uint(As[r + 8][ks + t4 + 4]);
            }
            uint32_t bf[8][2];
#pragma unroll
            for (int nt = 0; nt < 8; nt++) {
                int n = wn * 64 + nt * 8 + g4;
                bf[nt][0] = __float_as_uint(Bs[ks + t4][n]);
                bf[nt][1] = __float_as_uint(Bs[ks + t4 + 4][n]);
            }
#pragma unroll
            for (int mt = 0; mt < 2; mt++)
#pragma unroll
                for (int nt = 0; nt < 8; nt++)
                    mma_tf32(acc[mt][nt], af[mt], bf[nt]);
        }
        __syncthreads();
    }

    // store
#pragma unroll
    for (int mt = 0; mt < 2; mt++) {
        int r0 = blockIdx.y * BM + wm * 32 + mt * 16 + g4;
#pragma unroll
        for (int nt = 0; nt < 8; nt++) {
            int c = blockIdx.x * BN + wn * 64 + nt * 8 + 2 * t4;
            *(float2*)(C + (size_t)r0 * N + c)       = make_float2(acc[mt][nt][0], acc[mt][nt][1]);
            *(float2*)(C + (size_t)(r0 + 8) * N + c) = make_float2(acc[mt][nt][2], acc[mt][nt][3]);
        }
    }
}

// ---------------------------------------------------------------------------
// TF32 flash attention with tanh softcap + causal + GQA.
// Block = one (batch, head, 64-row Q tile). 256 threads = 8 warps (4x2).
// S = Q K^T via mma (warp: 16 rows x 32 keys); P round-trips through smem;
// O += P V via mma (warp: 16 rows x 64 dims).
// ---------------------------------------------------------------------------
#define APAD 132
#define PPAD 68
// floats: Qs 64*132 | Ks 64*132 | Vs 64*132 | Ps 64*68 | redm 64*2 | reds 64*2
#define OFF_Q  0
#define OFF_K  (64 * APAD)
#define OFF_V  (2 * 64 * APAD)
#define OFF_P  (3 * 64 * APAD)
#define OFF_RM (OFF_P + 64 * PPAD)
#define OFF_RS (OFF_RM + 128)
#define ATTN_SMEM_FLOATS (OFF_RS + 128)
#define ATTN_SMEM_BYTES  (ATTN_SMEM_FLOATS * 4)

__global__ __launch_bounds__(256, 1)
void attn_kernel(const float* __restrict__ qkv, float* __restrict__ out) {
    extern __shared__ float sm[];
    float* Qs = sm + OFF_Q;
    float* Ks = sm + OFF_K;
    float* Vs = sm + OFF_V;
    float* Ps = sm + OFF_P;
    float* redm = sm + OFF_RM;   // [64][2]
    float* reds = sm + OFF_RS;   // [64][2]

    const int qb = blockIdx.x;
    const int h  = blockIdx.y;
    const int b  = blockIdx.z;
    const int g  = h / REP;

    const int tid  = threadIdx.x;
    const int lane = tid & 31;
    const int warp = tid >> 5;
    const int wm = warp >> 1;          // 0..3
    const int wn = warp & 1;           // 0..1
    const int g4 = lane >> 2;          // 0..7
    const int t4 = lane & 3;           // 0..3

    const size_t rs = QKV_COLS;
    const float* qbase = qkv + ((size_t)b * S_LEN + (size_t)qb * 64) * rs + (size_t)h * HD;
    const float* kbase = qkv + (size_t)b * S_LEN * rs + (size_t)(NH * HD) + (size_t)g * HD;
    const float* vbase = kbase + (size_t)(NKV * HD);

    // load Q tile (tf32-converted)
    for (int idx = tid; idx < 64 * 32; idx += 256) {
        int r = idx >> 5, c = (idx & 31) * 4;
        float4 v = *(const float4*)(qbase + (size_t)r * rs + c);
        Qs[r * APAD + c + 0] = f2tf32(v.x); Qs[r * APAD + c + 1] = f2tf32(v.y);
        Qs[r * APAD + c + 2] = f2tf32(v.z); Qs[r * APAD + c + 3] = f2tf32(v.w);
    }

    const int rl0 = wm * 16 + g4;      // local row (0..63), second row = +8
    float m0 = -1e30f, m1 = -1e30f, l0 = 0.0f, l1 = 0.0f;
    float o[8][4];
#pragma unroll
    for (int nt = 0; nt < 8; nt++)
#pragma unroll
        for (int r = 0; r < 4; r++) o[nt][r] = 0.0f;

    for (int kt = 0; kt <= qb; kt++) {
        const float* kb = kbase + (size_t)kt * 64 * rs;
        const float* vb = vbase + (size_t)kt * 64 * rs;
        for (int idx = tid; idx < 64 * 32; idx += 256) {
            int r = idx >> 5, c = (idx & 31) * 4;
            float4 v = *(const float4*)(kb + (size_t)r * rs + c);
            Ks[r * APAD + c + 0] = f2tf32(v.x); Ks[r * APAD + c + 1] = f2tf32(v.y);
            Ks[r * APAD + c + 2] = f2tf32(v.z); Ks[r * APAD + c + 3] = f2tf32(v.w);
            v = *(const float4*)(vb + (size_t)r * rs + c);
            Vs[r * APAD + c + 0] = f2tf32(v.x); Vs[r * APAD + c + 1] = f2tf32(v.y);
            Vs[r * APAD + c + 2] = f2tf32(v.z); Vs[r * APAD + c + 3] = f2tf32(v.w);
        }
        __syncthreads();

        // S = Q K^T : warp computes 16 rows x 32 keys (4 n-tiles)
        float sfr[4][4];
#pragma unroll
        for (int nt = 0; nt < 4; nt++)
#pragma unroll
            for (int r = 0; r < 4; r++) sfr[nt][r] = 0.0f;

#pragma unroll
        for (int ks = 0; ks < 16; ks++) {
            int c = ks * 8 + t4;
            uint32_t af[4];
            af[0] = __float_as_uint(Qs[rl0 * APAD + c]);
            af[1] = __float_as_uint(Qs[(rl0 + 8) * APAD + c]);
            af[2] = __float_as_uint(Qs[rl0 * APAD + c + 4]);
            af[3] = __float_as_uint(Qs[(rl0 + 8) * APAD + c + 4]);
            uint32_t bf[4][2];
#pragma unroll
            for (int nt = 0; nt < 4; nt++) {
                int n = wn * 32 + nt * 8 + g4;
                bf[nt][0] = __float_as_uint(Ks[n * APAD + c]);
                bf[nt][1] = __float_as_uint(Ks[n * APAD + c + 4]);
            }
#pragma unroll
            for (int nt = 0; nt < 4; nt++) mma_tf32(sfr[nt], af, bf[nt]);
        }

        // softcap + causal mask + partial row max
        const bool diag = (kt == qb);
        float mx0 = -1e30f, mx1 = -1e30f;
#pragma unroll
        for (int nt = 0; nt < 4; nt++) {
            int cl = wn * 32 + nt * 8 + 2 * t4;
#pragma unroll
            for (int j = 0; j < 2; j++) {
                float v0 = SOFTCAP_F * tanhf(sfr[nt][j]     * (SCALE_F / SOFTCAP_F));
                float v1 = SOFTCAP_F * tanhf(sfr[nt][2 + j] * (SCALE_F / SOFTCAP_F));
                if (diag && (cl + j) > rl0)     v0 = -1e30f;
                if (diag && (cl + j) > rl0 + 8) v1 = -1e30f;
                sfr[nt][j] = v0; sfr[nt][2 + j] = v1;
                mx0 = fmaxf(mx0, v0); mx1 = fmaxf(mx1, v1);
            }
        }
        // reduce over the 4 lanes of the quad (cols within warp)
        mx0 = fmaxf(mx0, __shfl_xor_sync(0xffffffffu, mx0, 1));
        mx0 = fmaxf(mx0, __shfl_xor_sync(0xffffffffu, mx0, 2));
        mx1 = fmaxf(mx1, __shfl_xor_sync(0xffffffffu, mx1, 1));
        mx1 = fmaxf(mx1, __shfl_xor_sync(0xffffffffu, mx1, 2));
        if (t4 == 0) {
            redm[rl0 * 2 + wn]       = mx0;
            redm[(rl0 + 8) * 2 + wn] = mx1;
        }
        __syncthreads();

        float mn0 = fmaxf(m0, fmaxf(redm[rl0 * 2], redm[rl0 * 2 + 1]));
        float mn1 = fmaxf(m1, fmaxf(redm[(rl0 + 8) * 2], redm[(rl0 + 8) * 2 + 1]));
        float corr0 = __expf(m0 - mn0);
        float corr1 = __expf(m1 - mn1);

        float sum0 = 0.0f, sum1 = 0.0f;
#pragma unroll
        for (int nt = 0; nt < 4; nt++) {
            int cl = wn * 32 + nt * 8 + 2 * t4;
            float p00 = __expf(sfr[nt][0] - mn0);
            float p01 = __expf(sfr[nt][1] - mn0);
            float p10 = __expf(sfr[nt][2] - mn1);
            float p11 = __expf(sfr[nt][3] - mn1);
            sum0 += p00 + p01; sum1 += p10 + p11;
            *(float2*)&Ps[rl0 * PPAD + cl]       = make_float2(f2tf32(p00), f2tf32(p01));
            *(float2*)&Ps[(rl0 + 8) * PPAD + cl] = make_float2(f2tf32(p10), f2tf32(p11));
        }
        sum0 += __shfl_xor_sync(0xffffffffu, sum0, 1);
        sum0 += __shfl_xor_sync(0xffffffffu, sum0, 2);
        sum1 += __shfl_xor_sync(0xffffffffu, sum1, 1);
        sum1 += __shfl_xor_sync(0xffffffffu, sum1, 2);
        if (t4 == 0) {
            reds[rl0 * 2 + wn]       = sum0;
            reds[(rl0 + 8) * 2 + wn] = sum1;
        }
        __syncthreads();

        l0 = l0 * corr0 + reds[rl0 * 2] + reds[rl0 * 2 + 1];
        l1 = l1 * corr1 + reds[(rl0 + 8) * 2] + reds[(rl0 + 8) * 2 + 1];
        m0 = mn0; m1 = mn1;

        // rescale O
#pragma unroll
        for (int nt = 0; nt < 8; nt++) {
            o[nt][0] *= corr0; o[nt][1] *= corr0;
            o[nt][2] *= corr1; o[nt][3] *= corr1;
        }

        // O += P @ V : warp computes 16 rows x 64 dims (8 n-tiles), k=64 keys
#pragma unroll
        for (int ks = 0; ks < 8; ks++) {
            int kc = ks * 8 + t4;
            uint32_t af[4];
            af[0] = __float_as_uint(Ps[rl0 * PPAD + kc]);
            af[1] = __float_as_uint(Ps[(rl0 + 8) * PPAD + kc]);
            af[2] = __float_as_uint(Ps[rl0 * PPAD + kc + 4]);
            af[3] = __float_as_uint(Ps[(rl0 + 8) * PPAD + kc + 4]);
            uint32_t bf[8][2];
#pragma unroll
            for (int nt = 0; nt < 8; nt++) {
                int n = wn * 64 + nt * 8 + g4;
                bf[nt][0] = __float_as_uint(Vs[kc * APAD + n]);
                bf[nt][1] = __float_as_uint(Vs[(kc + 4) * APAD + n]);
            }
#pragma unroll
            for (int nt = 0; nt < 8; nt++) mma_tf32(o[nt], af, bf[nt]);
        }
        __syncthreads();
    }

    // epilogue: normalize + write
    float inv0 = 1.0f / l0;
    float inv1 = 1.0f / l1;
    size_t gr0 = (size_t)b * S_LEN + qb * 64 + rl0;
#pragma unroll
    for (int nt = 0; nt < 8; nt++) {
        int c = h * HD + wn * 64 + nt * 8 + 2 * t4;
        *(float2*)(out + gr0 * HIDDEN + c)       = make_float2(o[nt][0] * inv0, o[nt][1] * inv0);
        *(float2*)(out + (gr0 + 8) * HIDDEN + c) = make_float2(o[nt][2] * inv1, o[nt][3] * inv1);
    }
}

// ---------------------------------------------------------------------------
// Launch
// ---------------------------------------------------------------------------
extern "C" void kernel_launch(void* const* d_in, const int* in_sizes, int n_in,
                              void* d_out, int out_size) {
    (void)in_sizes; (void)n_in; (void)out_size;
    const float* hidden = (const float*)d_in[0];
    const float* Wqkv   = (const float*)d_in[1];
    const float* Wo     = (const float*)d_in[2];
    float* out = (float*)d_out;

    void* p;
    cudaGetSymbolAddress(&p, g_qkv);  float* qkv  = (float*)p;
    cudaGetSymbolAddress(&p, g_attn); float* attn = (float*)p;

    cudaFuncSetAttribute(attn_kernel, cudaFuncAttributeMaxDynamicSharedMemorySize,
                         ATTN_SMEM_BYTES);

    rope_table_kernel<<<(S_LEN * 64 + 255) / 256, 256>>>();

    // 1) QKV projection: [4096,2048] @ [2048,2560]
    gemm_tf32<<<dim3(QKV_COLS / 128, ROWS / 128), 256>>>(hidden, Wqkv, qkv,
                                                         ROWS, QKV_COLS, HIDDEN);
    // 2) RoPE on Q + K in place
    {
        int total = ROWS * 18 * 64;
        rope_apply_kernel<<<(total + 255) / 256, 256>>>(qkv);
    }
    // 3) Flash attention (tensor cores)
    attn_kernel<<<dim3(S_LEN / 64, NH, BATCH), 256, ATTN_SMEM_BYTES>>>(qkv, attn);

    // 4) Output projection: [4096,2048] @ [2048,2048]
    gemm_tf32<<<dim3(HIDDEN / 128, ROWS / 128), 256>>>(attn, Wo, out,
                                                       ROWS, HIDDEN, HIDDEN);
}

// round 3
// speedup vs baseline: 3.1139x; 1.0717x over previous
#include <cuda_runtime.h>
#include <math.h>
#include <stdint.h>

// Problem constants
#define BATCH   2
#define S_LEN   2048
#define HIDDEN  2048
#define NH      16
#define NKV     2
#define HD      128
#define REP     (NH / NKV)              // 8
#define QKV_COLS ((NH + 2 * NKV) * HD)  // 2560
#define ROWS    (BATCH * S_LEN)         // 4096
#define SCALE_F   0.08838834764831845f
#define SOFTCAP_F 30.0f

// Scratch (allocation-free rule: __device__ globals)
static __device__ float g_qkv[(size_t)ROWS * QKV_COLS];   // ~41.9 MB
static __device__ float g_attn[(size_t)ROWS * HIDDEN];    // ~33.5 MB
static __device__ float g_cos[S_LEN * (HD / 2)];
static __device__ float g_sin[S_LEN * (HD / 2)];

// ---------------------------------------------------------------------------
// Helpers
// ---------------------------------------------------------------------------
__device__ __forceinline__ float f2tf32(float x) {
    uint32_t u;
    asm("cvt.rna.tf32.f32 %0, %1;" : "=r"(u) : "f"(x));
    return __uint_as_float(u);
}

__device__ __forceinline__ void mma_tf32(float* d, const uint32_t* a, const uint32_t* b) {
    asm volatile(
        "mma.sync.aligned.m16n8k8.row.col.f32.tf32.tf32.f32 "
        "{%0,%1,%2,%3}, {%4,%5,%6,%7}, {%8,%9}, {%0,%1,%2,%3};\n"
        : "+f"(d[0]), "+f"(d[1]), "+f"(d[2]), "+f"(d[3])
        : "r"(a[0]), "r"(a[1]), "r"(a[2]), "r"(a[3]), "r"(b[0]), "r"(b[1]));
}

#define CP_ASYNC16(dst32, src) \
    asm volatile("cp.async.cg.shared.global [%0], [%1], 16;\n" :: "r"(dst32), "l"(src))
#define CP_COMMIT() asm volatile("cp.async.commit_group;\n")
#define CP_WAIT0()  asm volatile("cp.async.wait_group 0;\n")
#define CP_WAIT1()  asm volatile("cp.async.wait_group 1;\n")

// ---------------------------------------------------------------------------
// RoPE table in double precision (fast-math-proof; angles up to ~2047 rad)
// ---------------------------------------------------------------------------
__global__ void rope_table_kernel() {
    int i = blockIdx.x * blockDim.x + threadIdx.x;
    if (i >= S_LEN * 64) return;
    int s = i >> 6;
    int d = i & 63;
    double inv_freq = pow(10000.0, -(double)d / 64.0);
    double a = (double)s * inv_freq;
    g_cos[i] = (float)cos(a);
    g_sin[i] = (float)sin(a);
}

// RoPE on Q+K heads, in place; writes tf32-rounded values so the attention
// kernel can cp.async them straight into smem with no conversion.
__global__ void rope_apply_kernel(float* __restrict__ qkv) {
    int i = blockIdx.x * blockDim.x + threadIdx.x;
    const int total = ROWS * 18 * 64;
    if (i >= total) return;
    int d    = i & 63;
    int rest = i >> 6;
    int hh   = rest % 18;
    int row  = rest / 18;
    int s    = row & (S_LEN - 1);
    size_t base = (size_t)row * QKV_COLS +
                  (hh < 16 ? (size_t)hh * HD : (size_t)(NH * HD) + (size_t)(hh - 16) * HD);
    float c  = g_cos[(s << 6) + d];
    float sn = g_sin[(s << 6) + d];
    float x1 = qkv[base + d];
    float x2 = qkv[base + d + 64];
    qkv[base + d]      = f2tf32(x1 * c - x2 * sn);
    qkv[base + d + 64] = f2tf32(x1 * sn + x2 * c);
}

// ---------------------------------------------------------------------------
// TF32 GEMM with register double-buffering.
// BM=BN=128, BK=16, 256 threads = 8 warps (4x2), warp tile 32x64.
// If ROUND, output is tf32-rounded (consumed by attention without cvt).
// ---------------------------------------------------------------------------
template <bool ROUND>
__global__ __launch_bounds__(256, 2)
void gemm_tf32(const float* __restrict__ A, const float* __restrict__ B,
               float* __restrict__ C, int M, int N, int K) {
    constexpr int BM = 128, BN = 128, BK = 16;
    __shared__ float As[BM][20];
    __shared__ float Bs[BK][132];

    const int tid  = threadIdx.x;
    const int lane = tid & 31;
    const int warp = tid >> 5;
    const int wm = warp >> 1;
    const int wn = warp & 1;
    const int g4 = lane >> 2;
    const int t4 = lane & 3;

    const float* Ab = A + (size_t)blockIdx.y * BM * K;
    const float* Bb = B + (size_t)blockIdx.x * BN;

    const int aRow = tid >> 2;
    const int aCol = (tid & 3) * 4;
    const int bRow = tid >> 5;
    const int bCol = (tid & 31) * 4;

    float acc[2][8][4];
#pragma unroll
    for (int mt = 0; mt < 2; mt++)
#pragma unroll
        for (int nt = 0; nt < 8; nt++)
#pragma unroll
            for (int r = 0; r < 4; r++) acc[mt][nt][r] = 0.0f;

    // preload tile 0 into registers
    float4 pa0 = *(const float4*)(Ab + (size_t)aRow * K + aCol);
    float4 pa1 = *(const float4*)(Ab + (size_t)(aRow + 64) * K + aCol);
    float4 pb0 = *(const float4*)(Bb + (size_t)bRow * N + bCol);
    float4 pb1 = *(const float4*)(Bb + (size_t)(bRow + 8) * N + bCol);

    for (int k0 = 0; k0 < K; k0 += BK) {
        // store the prefetched tile (with tf32 rounding)
        As[aRow][aCol + 0] = f2tf32(pa0.x); As[aRow][aCol + 1] = f2tf32(pa0.y);
        As[aRow][aCol + 2] = f2tf32(pa0.z); As[aRow][aCol + 3] = f2tf32(pa0.w);
        As[aRow + 64][aCol + 0] = f2tf32(pa1.x); As[aRow + 64][aCol + 1] = f2tf32(pa1.y);
        As[aRow + 64][aCol + 2] = f2tf32(pa1.z); As[aRow + 64][aCol + 3] = f2tf32(pa1.w);
        Bs[bRow][bCol + 0] = f2tf32(pb0.x); Bs[bRow][bCol + 1] = f2tf32(pb0.y);
        Bs[bRow][bCol + 2] = f2tf32(pb0.z); Bs[bRow][bCol + 3] = f2tf32(pb0.w);
        Bs[bRow + 8][bCol + 0] = f2tf32(pb1.x); Bs[bRow + 8][bCol + 1] = f2tf32(pb1.y);
        Bs[bRow + 8][bCol + 2] = f2tf32(pb1.z); Bs[bRow + 8][bCol + 3] = f2tf32(pb1.w);
        __syncthreads();

        // prefetch next tile while computing this one
        if (k0 + BK < K) {
            pa0 = *(const float4*)(Ab + (size_t)aRow * K + k0 + BK + aCol);
            pa1 = *(const float4*)(Ab + (size_t)(aRow + 64) * K + k0 + BK + aCol);
            pb0 = *(const float4*)(Bb + (size_t)(k0 + BK + bRow) * N + bCol);
            pb1 = *(const float4*)(Bb + (size_t)(k0 + BK + bRow + 8) * N + bCol);
        }

#pragma unroll
        for (int ks = 0; ks < BK; ks += 8) {
            uint32_t af[2][4];
#pragma unroll
            for (int mt = 0; mt < 2; mt++) {
                int r = wm * 32 + mt * 16 + g4;
                af[mt][0] = __float_as_uint(As[r][ks + t4]);
                af[mt][1] = __float_as_uint(As[r + 8][ks + t4]);
                af[mt][2] = __float_as_uint(As[r][ks + t4 + 4]);
                af[mt][3] = __float_as_uint(As[r + 8][ks + t4 + 4]);
            }
            uint32_t bf[8][2];
#pragma unroll
            for (int nt = 0; nt < 8; nt++) {
                int n = wn * 64 + nt * 8 + g4;
                bf[nt][0] = __float_as_uint(Bs[ks + t4][n]);
                bf[nt][1] = __float_as_uint(Bs[ks + t4 + 4][n]);
            }
#pragma unroll
            for (int mt = 0; mt < 2; mt++)
#pragma unroll
                for (int nt = 0; nt < 8; nt++)
                    mma_tf32(acc[mt][nt], af[mt], bf[nt]);
        }
        __syncthreads();
    }

#pragma unroll
    for (int mt = 0; mt < 2; mt++) {
        int r0 = blockIdx.y * BM + wm * 32 + mt * 16 + g4;
#pragma unroll
        for (int nt = 0; nt < 8; nt++) {
            int c = blockIdx.x * BN + wn * 64 + nt * 8 + 2 * t4;
            float v0 = acc[mt][nt][0], v1 = acc[mt][nt][1];
            float v2 = acc[mt][nt][2], v3 = acc[mt][nt][3];
            if (ROUND) { v0 = f2tf32(v0); v1 = f2tf32(v1); v2 = f2tf32(v2); v3 = f2tf32(v3); }
            *(float2*)(C + (size_t)r0 * N + c)       = make_float2(v0, v1);
            *(float2*)(C + (size_t)(r0 + 8) * N + c) = make_float2(v2, v3);
        }
    }
}

// ---------------------------------------------------------------------------
// TF32 flash attention: cp.async double-buffered K/V, softcap + causal + GQA.
// Inputs (Q/K/V inside qkv) are pre-rounded to tf32, so no cvt on load.
// ---------------------------------------------------------------------------
#define APAD 132
#define PPAD 68
#define KVSTRIDE (64 * APAD)
#define OFF_Q  0
#define OFF_K  (64 * APAD)                 // 2 stages
#define OFF_V  (OFF_K + 2 * KVSTRIDE)      // 2 stages
#define OFF_P  (OFF_V + 2 * KVSTRIDE)
#define OFF_RM (OFF_P + 64 * PPAD)
#define OFF_RS (OFF_RM + 128)
#define ATTN_SMEM_FLOATS (OFF_RS + 128)
#define ATTN_SMEM_BYTES  (ATTN_SMEM_FLOATS * 4)

__global__ __launch_bounds__(256, 1)
void attn_kernel(const float* __restrict__ qkv, float* __restrict__ out) {
    extern __shared__ float sm[];
    float* Qs = sm + OFF_Q;
    float* Ks = sm + OFF_K;
    float* Vs = sm + OFF_V;
    float* Ps = sm + OFF_P;
    float* redm = sm + OFF_RM;
    float* reds = sm + OFF_RS;

    const int qb = (int)gridDim.x - 1 - (int)blockIdx.x;  // longest blocks first
    const int h  = blockIdx.y;
    const int b  = blockIdx.z;
    const int g  = h / REP;

    const int tid  = threadIdx.x;
    const int lane = tid & 31;
    const int warp = tid >> 5;
    const int wm = warp >> 1;
    const int wn = warp & 1;
    const int g4 = lane >> 2;
    const int t4 = lane & 3;

    const size_t rs = QKV_COLS;
    const float* qbase = qkv + ((size_t)b * S_LEN + (size_t)qb * 64) * rs + (size_t)h * HD;
    const float* kbase = qkv + (size_t)b * S_LEN * rs + (size_t)(NH * HD) + (size_t)g * HD;
    const float* vbase = kbase + (size_t)(NKV * HD);

    const int lr = tid >> 5;          // 0..7: this thread's row block step
    const int lc = (tid & 31) * 4;    // col within 128

    // prologue: cp.async Q tile + K/V tile 0 (group 0)
#pragma unroll
    for (int i = 0; i < 8; i++) {
        int r = i * 8 + lr;
        CP_ASYNC16((uint32_t)__cvta_generic_to_shared(&Qs[r * APAD + lc]),
                   qbase + (size_t)r * rs + lc);
    }
#pragma unroll
    for (int i = 0; i < 8; i++) {
        int r = i * 8 + lr;
        CP_ASYNC16((uint32_t)__cvta_generic_to_shared(&Ks[r * APAD + lc]),
                   kbase + (size_t)r * rs + lc);
        CP_ASYNC16((uint32_t)__cvta_generic_to_shared(&Vs[r * APAD + lc]),
                   vbase + (size_t)r * rs + lc);
    }
    CP_COMMIT();

    const int rl0 = wm * 16 + g4;
    float m0 = -1e30f, m1 = -1e30f, l0 = 0.0f, l1 = 0.0f;
    float o[8][4];
#pragma unroll
    for (int nt = 0; nt < 8; nt++)
#pragma unroll
        for (int r = 0; r < 4; r++) o[nt][r] = 0.0f;

    for (int kt = 0; kt <= qb; kt++) {
        const int cur = kt & 1;
        // issue prefetch of tile kt+1 into the other stage
        if (kt < qb) {
            const float* kb = kbase + (size_t)(kt + 1) * 64 * rs;
            const float* vb = vbase + (size_t)(kt + 1) * 64 * rs;
            float* Kd = Ks + (cur ^ 1) * KVSTRIDE;
            float* Vd = Vs + (cur ^ 1) * KVSTRIDE;
#pragma unroll
            for (int i = 0; i < 8; i++) {
                int r = i * 8 + lr;
                CP_ASYNC16((uint32_t)__cvta_generic_to_shared(&Kd[r * APAD + lc]),
                           kb + (size_t)r * rs + lc);
                CP_ASYNC16((uint32_t)__cvta_generic_to_shared(&Vd[r * APAD + lc]),
                           vb + (size_t)r * rs + lc);
            }
            CP_COMMIT();
            CP_WAIT1();   // current tile's group done; newest may be in flight
        } else {
            CP_WAIT0();
        }
        __syncthreads();

        const float* Ksc = Ks + cur * KVSTRIDE;
        const float* Vsc = Vs + cur * KVSTRIDE;

        // S = Q K^T
        float sfr[4][4];
#pragma unroll
        for (int nt = 0; nt < 4; nt++)
#pragma unroll
            for (int r = 0; r < 4; r++) sfr[nt][r] = 0.0f;

#pragma unroll
        for (int ks = 0; ks < 16; ks++) {
            int c = ks * 8 + t4;
            uint32_t af[4];
            af[0] = __float_as_uint(Qs[rl0 * APAD + c]);
            af[1] = __float_as_uint(Qs[(rl0 + 8) * APAD + c]);
            af[2] = __float_as_uint(Qs[rl0 * APAD + c + 4]);
            af[3] = __float_as_uint(Qs[(rl0 + 8) * APAD + c + 4]);
            uint32_t bf[4][2];
#pragma unroll
            for (int nt = 0; nt < 4; nt++) {
                int n = wn * 32 + nt * 8 + g4;
                bf[nt][0] = __float_as_uint(Ksc[n * APAD + c]);
                bf[nt][1] = __float_as_uint(Ksc[n * APAD + c + 4]);
            }
#pragma unroll
            for (int nt = 0; nt < 4; nt++) mma_tf32(sfr[nt], af, bf[nt]);
        }

        // softcap + causal mask + row max
        const bool diag = (kt == qb);
        float mx0 = -1e30f, mx1 = -1e30f;
#pragma unroll
        for (int nt = 0; nt < 4; nt++) {
            int cl = wn * 32 + nt * 8 + 2 * t4;
#pragma unroll
            for (int j = 0; j < 2; j++) {
                float v0 = SOFTCAP_F * tanhf(sfr[nt][j]     * (SCALE_F / SOFTCAP_F));
                float v1 = SOFTCAP_F * tanhf(sfr[nt][2 + j] * (SCALE_F / SOFTCAP_F));
                if (diag && (cl + j) > rl0)     v0 = -1e30f;
                if (diag && (cl + j) > rl0 + 8) v1 = -1e30f;
                sfr[nt][j] = v0; sfr[nt][2 + j] = v1;
                mx0 = fmaxf(mx0, v0); mx1 = fmaxf(mx1, v1);
            }
        }
        mx0 = fmaxf(mx0, __shfl_xor_sync(0xffffffffu, mx0, 1));
        mx0 = fmaxf(mx0, __shfl_xor_sync(0xffffffffu, mx0, 2));
        mx1 = fmaxf(mx1, __shfl_xor_sync(0xffffffffu, mx1, 1));
        mx1 = fmaxf(mx1, __shfl_xor_sync(0xffffffffu, mx1, 2));
        if (t4 == 0) {
            redm[rl0 * 2 + wn]       = mx0;
            redm[(rl0 + 8) * 2 + wn] = mx1;
        }
        __syncthreads();

        float mn0 = fmaxf(m0, fmaxf(redm[rl0 * 2], redm[rl0 * 2 + 1]));
        float mn1 = fmaxf(m1, fmaxf(redm[(rl0 + 8) * 2], redm[(rl0 + 8) * 2 + 1]));
        float corr0 = __expf(m0 - mn0);
        float corr1 = __expf(m1 - mn1);

        float sum0 = 0.0f, sum1 = 0.0f;
#pragma unroll
        for (int nt = 0; nt < 4; nt++) {
            int cl = wn * 32 + nt * 8 + 2 * t4;
            float p00 = __expf(sfr[nt][0] - mn0);
            float p01 = __expf(sfr[nt][1] - mn0);
            float p10 = __expf(sfr[nt][2] - mn1);
            float p11 = __expf(sfr[nt][3] - mn1);
            sum0 += p00 + p01; sum1 += p10 + p11;
            *(float2*)&Ps[rl0 * PPAD + cl]       = make_float2(f2tf32(p00), f2tf32(p01));
            *(float2*)&Ps[(rl0 + 8) * PPAD + cl] = make_float2(f2tf32(p10), f2tf32(p11));
        }
        sum0 += __shfl_xor_sync(0xffffffffu, sum0, 1);
        sum0 += __shfl_xor_sync(0xffffffffu, sum0, 2);
        sum1 += __shfl_xor_sync(0xffffffffu, sum1, 1);
        sum1 += __shfl_xor_sync(0xffffffffu, sum1, 2);
        if (t4 == 0) {
            reds[rl0 * 2 + wn]       = sum0;
            reds[(rl0 + 8) * 2 + wn] = sum1;
        }
        __syncthreads();

        l0 = l0 * corr0 + reds[rl0 * 2] + reds[rl0 * 2 + 1];
        l1 = l1 * corr1 + reds[(rl0 + 8) * 2] + reds[(rl0 + 8) * 2 + 1];
        m0 = mn0; m1 = mn1;

#pragma unroll
        for (int nt = 0; nt < 8; nt++) {
            o[nt][0] *= corr0; o[nt][1] *= corr0;
            o[nt][2] *= corr1; o[nt][3] *= corr1;
        }

        // O += P @ V
#pragma unroll
        for (int ks = 0; ks < 8; ks++) {
            int kc = ks * 8 + t4;
            uint32_t af[4];
            af[0] = __float_as_uint(Ps[rl0 * PPAD + kc]);
            af[1] = __float_as_uint(Ps[(rl0 + 8) * PPAD + kc]);
            af[2] = __float_as_uint(Ps[rl0 * PPAD + kc + 4]);
            af[3] = __float_as_uint(Ps[(rl0 + 8) * PPAD + kc + 4]);
            uint32_t bf[8][2];
#pragma unroll
            for (int nt = 0; nt < 8; nt++) {
                int n = wn * 64 + nt * 8 + g4;
                bf[nt][0] = __float_as_uint(Vsc[kc * APAD + n]);
                bf[nt][1] = __float_as_uint(Vsc[(kc + 4) * APAD + n]);
            }
#pragma unroll
            for (int nt = 0; nt < 8; nt++) mma_tf32(o[nt], af, bf[nt]);
        }
        __syncthreads();   // stage cur free for reuse by next prefetch
    }

    float inv0 = 1.0f / l0;
    float inv1 = 1.0f / l1;
    size_t gr0 = (size_t)b * S_LEN + qb * 64 + rl0;
#pragma unroll
    for (int nt = 0; nt < 8; nt++) {
        int c = h * HD + wn * 64 + nt * 8 + 2 * t4;
        *(float2*)(out + gr0 * HIDDEN + c)       = make_float2(o[nt][0] * inv0, o[nt][1] * inv0);
        *(float2*)(out + (gr0 + 8) * HIDDEN + c) = make_float2(o[nt][2] * inv1, o[nt][3] * inv1);
    }
}

// ---------------------------------------------------------------------------
// Launch
// ---------------------------------------------------------------------------
extern "C" void kernel_launch(void* const* d_in, const int* in_sizes, int n_in,
                              void* d_out, int out_size) {
    (void)in_sizes; (void)n_in; (void)out_size;
    const float* hidden = (const float*)d_in[0];
    const float* Wqkv   = (const float*)d_in[1];
    const float* Wo     = (const float*)d_in[2];
    float* out = (float*)d_out;

    void* p;
    cudaGetSymbolAddress(&p, g_qkv);  float* qkv  = (float*)p;
    cudaGetSymbolAddress(&p, g_attn); float* attn = (float*)p;

    cudaFuncSetAttribute(attn_kernel, cudaFuncAttributeMaxDynamicSharedMemorySize,
                         ATTN_SMEM_BYTES);

    rope_table_kernel<<<(S_LEN * 64 + 255) / 256, 256>>>();

    // 1) QKV projection (tf32-rounded output feeds attention directly)
    gemm_tf32<true><<<dim3(QKV_COLS / 128, ROWS / 128), 256>>>(hidden, Wqkv, qkv,
                                                               ROWS, QKV_COLS, HIDDEN);
    // 2) RoPE on Q + K (writes tf32-rounded)
    {
        int total = ROWS * 18 * 64;
        rope_apply_kernel<<<(total + 255) / 256, 256>>>(qkv);
    }
    // 3) Flash attention (cp.async pipelined)
    attn_kernel<<<dim3(S_LEN / 64, NH, BATCH), 256, ATTN_SMEM_BYTES>>>(qkv, attn);

    // 4) Output projection
    gemm_tf32<false><<<dim3(HIDDEN / 128, ROWS / 128), 256>>>(attn, Wo, out,
                                                              ROWS, HIDDEN, HIDDEN);
}

// round 4
// speedup vs baseline: 7.5131x; 2.4128x over previous
#include <cuda_runtime.h>
#include <cuda_fp16.h>
#include <math.h>
#include <stdint.h>

// Problem constants
#define BATCH   2
#define S_LEN   2048
#define HIDDEN  2048
#define NH      16
#define NKV     2
#define HD      128
#define REP     (NH / NKV)              // 8
#define QKV_COLS ((NH + 2 * NKV) * HD)  // 2560
#define ROWS    (BATCH * S_LEN)         // 4096
#define SCALE_F   0.08838834764831845f
#define SOFTCAP_F 30.0f

// Scratch (__device__ globals; 16B-aligned for cp.async/ldmatrix)
static __device__ __align__(16) __half g_hh[(size_t)ROWS * HIDDEN];
static __device__ __align__(16) __half g_wqkvh[(size_t)HIDDEN * QKV_COLS];
static __device__ __align__(16) __half g_woh[(size_t)HIDDEN * HIDDEN];
static __device__ __align__(16) __half g_qkvh[(size_t)ROWS * QKV_COLS];
static __device__ __align__(16) __half g_attnh[(size_t)ROWS * HIDDEN];
static __device__ float g_cos[S_LEN * 64];
static __device__ float g_sin[S_LEN * 64];

// ---------------------------------------------------------------------------
// PTX helpers
// ---------------------------------------------------------------------------
__device__ __forceinline__ void mma_f16(float* d, const uint32_t* a, const uint32_t* b) {
    asm volatile(
        "mma.sync.aligned.m16n8k16.row.col.f32.f16.f16.f32 "
        "{%0,%1,%2,%3}, {%4,%5,%6,%7}, {%8,%9}, {%0,%1,%2,%3};\n"
        : "+f"(d[0]), "+f"(d[1]), "+f"(d[2]), "+f"(d[3])
        : "r"(a[0]), "r"(a[1]), "r"(a[2]), "r"(a[3]), "r"(b[0]), "r"(b[1]));
}
__device__ __forceinline__ void ldsm4(uint32_t* r, uint32_t addr) {
    asm volatile("ldmatrix.sync.aligned.m8n8.x4.shared.b16 {%0,%1,%2,%3}, [%4];"
                 : "=r"(r[0]), "=r"(r[1]), "=r"(r[2]), "=r"(r[3]) : "r"(addr));
}
__device__ __forceinline__ void ldsm4t(uint32_t* r, uint32_t addr) {
    asm volatile("ldmatrix.sync.aligned.m8n8.x4.trans.shared.b16 {%0,%1,%2,%3}, [%4];"
                 : "=r"(r[0]), "=r"(r[1]), "=r"(r[2]), "=r"(r[3]) : "r"(addr));
}
#define CP_ASYNC16(dst32, src) \
    asm volatile("cp.async.cg.shared.global [%0], [%1], 16;\n" :: "r"(dst32), "l"(src))
#define CP_COMMIT() asm volatile("cp.async.commit_group;\n")
#define CP_WAIT0()  asm volatile("cp.async.wait_group 0;\n")

// ---------------------------------------------------------------------------
// f32 -> f16 conversion (vectorized)
// ---------------------------------------------------------------------------
__global__ void f2h_kernel(const float* __restrict__ in, __half* __restrict__ out, int n2) {
    int i = blockIdx.x * blockDim.x + threadIdx.x;
    if (i < n2) {
        float2 v = ((const float2*)in)[i];
        ((__half2*)out)[i] = __floats2half2_rn(v.x, v.y);
    }
}

// ---------------------------------------------------------------------------
// RoPE table in double precision (fast-math-proof; angles up to ~2047 rad)
// ---------------------------------------------------------------------------
__global__ void rope_table_kernel() {
    int i = blockIdx.x * blockDim.x + threadIdx.x;
    if (i >= S_LEN * 64) return;
    int s = i >> 6;
    int d = i & 63;
    double inv_freq = pow(10000.0, -(double)d / 64.0);
    double a = (double)s * inv_freq;
    g_cos[i] = (float)cos(a);
    g_sin[i] = (float)sin(a);
}

// RoPE applied in-place on the half qkv buffer (Q heads 0-15, K heads 16-17).
__global__ void rope_apply_h(__half* __restrict__ q) {
    int i = blockIdx.x * blockDim.x + threadIdx.x;
    const int total = ROWS * 18 * 32;
    if (i >= total) return;
    int dp   = (i & 31) * 2;
    int rest = i >> 5;
    int hh   = rest % 18;
    int row  = rest / 18;
    int s    = row & (S_LEN - 1);
    size_t base = (size_t)row * QKV_COLS +
                  (hh < 16 ? (size_t)hh * HD : (size_t)(NH * HD) + (size_t)(hh - 16) * HD);
    float2 c  = *(const float2*)&g_cos[(s << 6) + dp];
    float2 sn = *(const float2*)&g_sin[(s << 6) + dp];
    float2 x1 = __half22float2(*(__half2*)&q[base + dp]);
    float2 x2 = __half22float2(*(__half2*)&q[base + dp + 64]);
    *(__half2*)&q[base + dp]      = __floats2half2_rn(x1.x * c.x - x2.x * sn.x,
                                                      x1.y * c.y - x2.y * sn.y);
    *(__half2*)&q[base + dp + 64] = __floats2half2_rn(x1.x * sn.x + x2.x * c.x,
                                                      x1.y * sn.y + x2.y * c.y);
}

// ---------------------------------------------------------------------------
// FP16 GEMM (f32 accumulate): C[M,N] = A[M,K] @ B[K,N], both half row-major.
// BM=BN=128, BK=32, 256 threads = 8 warps (4x2), warp tile 32x64.
// cp.async double-buffered smem; ldmatrix fragment loads.
// ---------------------------------------------------------------------------
template <bool OUTHALF>
__global__ __launch_bounds__(256, 2)
void gemm_f16(const __half* __restrict__ A, const __half* __restrict__ B,
              void* __restrict__ Cv, int M, int N, int K) {
    __shared__ __align__(16) __half smem[2 * 128 * 40 + 2 * 32 * 136];
    const uint32_t sbase = (uint32_t)__cvta_generic_to_shared(smem);
    const uint32_t sAs[2] = {sbase, sbase + 128 * 40 * 2};
    const uint32_t sBs[2] = {sbase + 2 * 128 * 40 * 2, sbase + 2 * 128 * 40 * 2 + 32 * 136 * 2};

    const int tid = threadIdx.x, lane = tid & 31, warp = tid >> 5;
    const int wm = warp >> 1, wn = warp & 1, g4 = lane >> 2, t4 = lane & 3;

    const __half* Ab = A + (size_t)blockIdx.y * 128 * K;
    const __half* Bb = B + (size_t)blockIdx.x * 128;

    // ldmatrix lane geometry
    const int lsub  = lane >> 3;
    const int arow  = ((lsub & 1) << 3) + (lane & 7);   // A: row within 16
    const int acolh = (lsub >> 1) << 3;                 // A: k offset 0/8
    const int vrow  = lane & 15;                        // B(trans): k row within 16
    const int vcolh = (lane >> 4) << 3;                 // B(trans): n offset 0/8

    float acc[2][8][4];
#pragma unroll
    for (int mt = 0; mt < 2; mt++)
#pragma unroll
        for (int nt = 0; nt < 8; nt++)
#pragma unroll
            for (int r = 0; r < 4; r++) acc[mt][nt][r] = 0.0f;

    // prologue: stage 0 = tile k0=0
    {
#pragma unroll
        for (int i = 0; i < 2; i++) {
            int g = tid + 256 * i;
            int r = g >> 2, ch = g & 3;
            CP_ASYNC16(sAs[0] + r * 80 + ch * 16, Ab + (size_t)r * K + ch * 8);
        }
#pragma unroll
        for (int i = 0; i < 2; i++) {
            int g = tid + 256 * i;
            int r = g >> 4, ch = g & 15;
            CP_ASYNC16(sBs[0] + r * 272 + ch * 16, Bb + (size_t)r * N + ch * 8);
        }
        CP_COMMIT();
    }

    for (int k0 = 0; k0 < K; k0 += 32) {
        const int cur = (k0 >> 5) & 1;
        CP_WAIT0();
        __syncthreads();
        if (k0 + 32 < K) {
            const int nxt = cur ^ 1;
#pragma unroll
            for (int i = 0; i < 2; i++) {
                int g = tid + 256 * i;
                int r = g >> 2, ch = g & 3;
                CP_ASYNC16(sAs[nxt] + r * 80 + ch * 16, Ab + (size_t)r * K + k0 + 32 + ch * 8);
            }
#pragma unroll
            for (int i = 0; i < 2; i++) {
                int g = tid + 256 * i;
                int r = g >> 4, ch = g & 15;
                CP_ASYNC16(sBs[nxt] + r * 272 + ch * 16, Bb + (size_t)(k0 + 32 + r) * N + ch * 8);
            }
            CP_COMMIT();
        }

#pragma unroll
        for (int ks = 0; ks < 2; ks++) {
            uint32_t af[2][4];
#pragma unroll
            for (int mt = 0; mt < 2; mt++)
                ldsm4(af[mt], sAs[cur] + (wm * 32 + mt * 16 + arow) * 80 + (ks * 16 + acolh) * 2);
            uint32_t bf[8][2];
#pragma unroll
            for (int t = 0; t < 4; t++) {
                uint32_t v[4];
                ldsm4t(v, sBs[cur] + (ks * 16 + vrow) * 272 + (wn * 64 + t * 16 + vcolh) * 2);
                bf[2 * t][0] = v[0]; bf[2 * t][1] = v[1];
                bf[2 * t + 1][0] = v[2]; bf[2 * t + 1][1] = v[3];
            }
#pragma unroll
            for (int mt = 0; mt < 2; mt++)
#pragma unroll
                for (int nt = 0; nt < 8; nt++)
                    mma_f16(acc[mt][nt], af[mt], bf[nt]);
        }
    }

#pragma unroll
    for (int mt = 0; mt < 2; mt++) {
        int r0 = blockIdx.y * 128 + wm * 32 + mt * 16 + g4;
#pragma unroll
        for (int nt = 0; nt < 8; nt++) {
            int c = blockIdx.x * 128 + wn * 64 + nt * 8 + 2 * t4;
            if (OUTHALF) {
                __half* C = (__half*)Cv;
                *(__half2*)(C + (size_t)r0 * N + c)       = __floats2half2_rn(acc[mt][nt][0], acc[mt][nt][1]);
                *(__half2*)(C + (size_t)(r0 + 8) * N + c) = __floats2half2_rn(acc[mt][nt][2], acc[mt][nt][3]);
            } else {
                float* C = (float*)Cv;
                *(float2*)(C + (size_t)r0 * N + c)       = make_float2(acc[mt][nt][0], acc[mt][nt][1]);
                *(float2*)(C + (size_t)(r0 + 8) * N + c) = make_float2(acc[mt][nt][2], acc[mt][nt][3]);
            }
        }
    }
}

// ---------------------------------------------------------------------------
// FP16 flash attention with softcap + causal + GQA.
// BM=64 Q rows, BN=64 keys, 256 threads = 8 warps (4 row-groups x 2 key-halves).
// cp.async double-buffered K/V (half source, no conversion); ldmatrix frags.
// Smem 95 KB -> 2 CTAs/SM.
// ---------------------------------------------------------------------------
#define QP_B 272                        // 136 halves per row
#define PP_B 144                        // 72 halves per row
#define OFF_Q   0
#define OFF_K   17408
#define KV_ST   17408
#define OFF_V   52224
#define OFF_P   87040
#define OFF_RM  96256
#define OFF_RS  96768
#define ATTN_SMEM_BYTES 97280

__global__ __launch_bounds__(256, 2)
void attn_kernel(const __half* __restrict__ qkv, __half* __restrict__ out) {
    extern __shared__ __align__(16) char smraw[];
    float* redm = (float*)(smraw + OFF_RM);   // [64][2]
    float* reds = (float*)(smraw + OFF_RS);   // [64][2]
    const uint32_t sbase = (uint32_t)__cvta_generic_to_shared(smraw);

    const int qb = (int)gridDim.x - 1 - (int)blockIdx.x;  // longest first
    const int h  = blockIdx.y;
    const int b  = blockIdx.z;
    const int g  = h / REP;

    const int tid = threadIdx.x, lane = tid & 31, warp = tid >> 5;
    const int wm = warp >> 1, wn = warp & 1, g4 = lane >> 2, t4 = lane & 3;

    const size_t rs = QKV_COLS;
    const __half* qbase = qkv + ((size_t)b * S_LEN + (size_t)qb * 64) * rs + (size_t)h * HD;
    const __half* kbase = qkv + (size_t)b * S_LEN * rs + (size_t)(NH * HD) + (size_t)g * HD;
    const __half* vbase = kbase + (size_t)(NKV * HD);

    // tile-load geometry: 64 rows x 16 chunks of 16B
    const int lrow = tid >> 4;     // 0..15 (+16*i)
    const int lch  = tid & 15;

    // ldmatrix lane geometry
    const int lsub  = lane >> 3;
    const int arow  = ((lsub & 1) << 3) + (lane & 7);
    const int acolh = (lsub >> 1) << 3;
    const int krow  = ((lane >> 4) << 3) + (lane & 7);   // K frag: key row within 16
    const int kcolh = ((lane >> 3) & 1) << 3;            // K frag: k offset 0/8
    const int vrow  = lane & 15;                          // V(trans): key row within 16
    const int vcolh = (lane >> 4) << 3;                   // V(trans): dim offset 0/8

    // prologue: Q + K/V tile 0 into stage 0
#pragma unroll
    for (int i = 0; i < 4; i++) {
        int r = lrow + 16 * i;
        CP_ASYNC16(sbase + OFF_Q + r * QP_B + lch * 16, qbase + (size_t)r * rs + lch * 8);
    }
#pragma unroll
    for (int i = 0; i < 4; i++) {
        int r = lrow + 16 * i;
        CP_ASYNC16(sbase + OFF_K + r * QP_B + lch * 16, kbase + (size_t)r * rs + lch * 8);
        CP_ASYNC16(sbase + OFF_V + r * QP_B + lch * 16, vbase + (size_t)r * rs + lch * 8);
    }
    CP_COMMIT();

    const int rl0 = wm * 16 + g4;
    float m0 = -1e30f, m1 = -1e30f, l0 = 0.0f, l1 = 0.0f;
    float o[8][4];
#pragma unroll
    for (int nt = 0; nt < 8; nt++)
#pragma unroll
        for (int r = 0; r < 4; r++) o[nt][r] = 0.0f;

    const uint32_t aQ = sbase + OFF_Q + (wm * 16 + arow) * QP_B + acolh * 2;
    const uint32_t aP = sbase + OFF_P + (wm * 16 + arow) * PP_B + acolh * 2;

    for (int kt = 0; kt <= qb; kt++) {
        const int cur = kt & 1;
        CP_WAIT0();
        __syncthreads();   // stage data ready; prior iter's readers done

        // prefetch next K/V into the other stage (now provably free)
        if (kt < qb) {
            const __half* kb = kbase + (size_t)(kt + 1) * 64 * rs;
            const __half* vb = vbase + (size_t)(kt + 1) * 64 * rs;
            const uint32_t kd = sbase + OFF_K + (cur ^ 1) * KV_ST;
            const uint32_t vd = sbase + OFF_V + (cur ^ 1) * KV_ST;
#pragma unroll
            for (int i = 0; i < 4; i++) {
                int r = lrow + 16 * i;
                CP_ASYNC16(kd + r * QP_B + lch * 16, kb + (size_t)r * rs + lch * 8);
                CP_ASYNC16(vd + r * QP_B + lch * 16, vb + (size_t)r * rs + lch * 8);
            }
            CP_COMMIT();
        }

        const uint32_t bK = sbase + OFF_K + cur * KV_ST + (wn * 32 + krow) * QP_B + kcolh * 2;
        const uint32_t bV = sbase + OFF_V + cur * KV_ST + vrow * QP_B + (wn * 64 + vcolh) * 2;

        // ---- S = Q K^T ----
        float sfr[4][4];
#pragma unroll
        for (int nt = 0; nt < 4; nt++)
#pragma unroll
            for (int r = 0; r < 4; r++) sfr[nt][r] = 0.0f;

#pragma unroll
        for (int ks = 0; ks < 8; ks++) {
            uint32_t af[4];
            ldsm4(af, aQ + ks * 32);
            uint32_t b0[4], b1[4];
            ldsm4(b0, bK + ks * 32);
            ldsm4(b1, bK + 16 * QP_B + ks * 32);
            mma_f16(sfr[0], af, &b0[0]);
            mma_f16(sfr[1], af, &b0[2]);
            mma_f16(sfr[2], af, &b1[0]);
            mma_f16(sfr[3], af, &b1[2]);
        }

        // ---- softcap + causal + row max ----
        const bool diag = (kt == qb);
        float mx0 = -1e30f, mx1 = -1e30f;
#pragma unroll
        for (int nt = 0; nt < 4; nt++) {
            int cl = wn * 32 + nt * 8 + 2 * t4;
#pragma unroll
            for (int j = 0; j < 2; j++) {
                float v0 = SOFTCAP_F * tanhf(sfr[nt][j]     * (SCALE_F / SOFTCAP_F));
                float v1 = SOFTCAP_F * tanhf(sfr[nt][2 + j] * (SCALE_F / SOFTCAP_F));
                if (diag && (cl + j) > rl0)     v0 = -1e30f;
                if (diag && (cl + j) > rl0 + 8) v1 = -1e30f;
                sfr[nt][j] = v0; sfr[nt][2 + j] = v1;
                mx0 = fmaxf(mx0, v0); mx1 = fmaxf(mx1, v1);
            }
        }
        mx0 = fmaxf(mx0, __shfl_xor_sync(0xffffffffu, mx0, 1));
        mx0 = fmaxf(mx0, __shfl_xor_sync(0xffffffffu, mx0, 2));
        mx1 = fmaxf(mx1, __shfl_xor_sync(0xffffffffu, mx1, 1));
        mx1 = fmaxf(mx1, __shfl_xor_sync(0xffffffffu, mx1, 2));
        if (t4 == 0) {
            redm[rl0 * 2 + wn]       = mx0;
            redm[(rl0 + 8) * 2 + wn] = mx1;
        }
        __syncthreads();

        float mn0 = fmaxf(m0, fmaxf(redm[rl0 * 2], redm[rl0 * 2 + 1]));
        float mn1 = fmaxf(m1, fmaxf(redm[(rl0 + 8) * 2], redm[(rl0 + 8) * 2 + 1]));
        float corr0 = __expf(m0 - mn0);
        float corr1 = __expf(m1 - mn1);

        __half* Ps = (__half*)(smraw + OFF_P);
        float sum0 = 0.0f, sum1 = 0.0f;
#pragma unroll
        for (int nt = 0; nt < 4; nt++) {
            int cl = wn * 32 + nt * 8 + 2 * t4;
            float p00 = __expf(sfr[nt][0] - mn0);
            float p01 = __expf(sfr[nt][1] - mn0);
            float p10 = __expf(sfr[nt][2] - mn1);
            float p11 = __expf(sfr[nt][3] - mn1);
            sum0 += p00 + p01; sum1 += p10 + p11;
            *(__half2*)&Ps[rl0 * 72 + cl]       = __floats2half2_rn(p00, p01);
            *(__half2*)&Ps[(rl0 + 8) * 72 + cl] = __floats2half2_rn(p10, p11);
        }
        sum0 += __shfl_xor_sync(0xffffffffu, sum0, 1);
        sum0 += __shfl_xor_sync(0xffffffffu, sum0, 2);
        sum1 += __shfl_xor_sync(0xffffffffu, sum1, 1);
        sum1 += __shfl_xor_sync(0xffffffffu, sum1, 2);
        if (t4 == 0) {
            reds[rl0 * 2 + wn]       = sum0;
            reds[(rl0 + 8) * 2 + wn] = sum1;
        }
        __syncthreads();

        l0 = l0 * corr0 + reds[rl0 * 2] + reds[rl0 * 2 + 1];
        l1 = l1 * corr1 + reds[(rl0 + 8) * 2] + reds[(rl0 + 8) * 2 + 1];
        m0 = mn0; m1 = mn1;

#pragma unroll
        for (int nt = 0; nt < 8; nt++) {
            o[nt][0] *= corr0; o[nt][1] *= corr0;
            o[nt][2] *= corr1; o[nt][3] *= corr1;
        }

        // ---- O += P @ V ----
#pragma unroll
        for (int kk = 0; kk < 4; kk++) {
            uint32_t af[4];
            ldsm4(af, aP + kk * 32);
#pragma unroll
            for (int t = 0; t < 4; t++) {
                uint32_t v[4];
                ldsm4t(v, bV + kk * 16 * QP_B + t * 32);
                mma_f16(o[2 * t],     af, &v[0]);
                mma_f16(o[2 * t + 1], af, &v[2]);
            }
        }
        // next iteration's CP_WAIT0 + __syncthreads gates Ps/stage reuse
    }

    float inv0 = 1.0f / l0;
    float inv1 = 1.0f / l1;
    size_t gr0 = (size_t)b * S_LEN + qb * 64 + rl0;
#pragma unroll
    for (int nt = 0; nt < 8; nt++) {
        int c = h * HD + wn * 64 + nt * 8 + 2 * t4;
        *(__half2*)(out + gr0 * HIDDEN + c)       = __floats2half2_rn(o[nt][0] * inv0, o[nt][1] * inv0);
        *(__half2*)(out + (gr0 + 8) * HIDDEN + c) = __floats2half2_rn(o[nt][2] * inv1, o[nt][3] * inv1);
    }
}

// ---------------------------------------------------------------------------
// Launch
// ---------------------------------------------------------------------------
extern "C" void kernel_launch(void* const* d_in, const int* in_sizes, int n_in,
                              void* d_out, int out_size) {
    (void)in_sizes; (void)n_in; (void)out_size;
    const float* hidden = (const float*)d_in[0];
    const float* Wqkv   = (const float*)d_in[1];
    const float* Wo     = (const float*)d_in[2];
    float* out = (float*)d_out;

    void* p;
    cudaGetSymbolAddress(&p, g_hh);    __half* hh    = (__half*)p;
    cudaGetSymbolAddress(&p, g_wqkvh); __half* wqkvh = (__half*)p;
    cudaGetSymbolAddress(&p, g_woh);   __half* woh   = (__half*)p;
    cudaGetSymbolAddress(&p, g_qkvh);  __half* qkvh  = (__half*)p;
    cudaGetSymbolAddress(&p, g_attnh); __half* attnh = (__half*)p;

    cudaFuncSetAttribute(attn_kernel, cudaFuncAttributeMaxDynamicSharedMemorySize,
                         ATTN_SMEM_BYTES);

    rope_table_kernel<<<(S_LEN * 64 + 255) / 256, 256>>>();

    // convert inputs to half
    {
        int n2;
        n2 = ROWS * HIDDEN / 2;
        f2h_kernel<<<(n2 + 255) / 256, 256>>>(hidden, hh, n2);
        n2 = HIDDEN * QKV_COLS / 2;
        f2h_kernel<<<(n2 + 255) / 256, 256>>>(Wqkv, wqkvh, n2);
        n2 = HIDDEN * HIDDEN / 2;
        f2h_kernel<<<(n2 + 255) / 256, 256>>>(Wo, woh, n2);
    }

    // 1) QKV projection (half output)
    gemm_f16<true><<<dim3(QKV_COLS / 128, ROWS / 128), 256>>>(hh, wqkvh, qkvh,
                                                              ROWS, QKV_COLS, HIDDEN);
    // 2) RoPE on Q + K in place (half)
    {
        int total = ROWS * 18 * 32;
        rope_apply_h<<<(total + 255) / 256, 256>>>(qkvh);
    }
    // 3) Flash attention (fp16 tensor cores, half output)
    attn_kernel<<<dim3(S_LEN / 64, NH, BATCH), 256, ATTN_SMEM_BYTES>>>(qkvh, attnh);

    // 4) Output projection (float output)
    gemm_f16<false><<<dim3(HIDDEN / 128, ROWS / 128), 256>>>(attnh, woh, out,
                                                             ROWS, HIDDEN, HIDDEN);
}

// round 5
// speedup vs baseline: 7.8079x; 1.0392x over previous
#include <cuda_runtime.h>
#include <cuda_fp16.h>
#include <math.h>
#include <stdint.h>

// Problem constants
#define BATCH   2
#define S_LEN   2048
#define HIDDEN  2048
#define NH      16
#define NKV     2
#define HD      128
#define REP     (NH / NKV)              // 8
#define QKV_COLS ((NH + 2 * NKV) * HD)  // 2560
#define ROWS    (BATCH * S_LEN)         // 4096
#define SCALE_F   0.08838834764831845f
#define SOFTCAP_F 30.0f

// Scratch (__device__ globals; 16B-aligned for cp.async/ldmatrix)
static __device__ __align__(16) __half g_hh[(size_t)ROWS * HIDDEN];
static __device__ __align__(16) __half g_wqkvh[(size_t)HIDDEN * QKV_COLS];
static __device__ __align__(16) __half g_woh[(size_t)HIDDEN * HIDDEN];
static __device__ __align__(16) __half g_qkvh[(size_t)ROWS * QKV_COLS];
static __device__ __align__(16) __half g_attnh[(size_t)ROWS * HIDDEN];
static __device__ float g_cos[S_LEN * 64];
static __device__ float g_sin[S_LEN * 64];

// ---------------------------------------------------------------------------
// PTX helpers
// ---------------------------------------------------------------------------
__device__ __forceinline__ void mma_f16(float* d, const uint32_t* a, const uint32_t* b) {
    asm volatile(
        "mma.sync.aligned.m16n8k16.row.col.f32.f16.f16.f32 "
        "{%0,%1,%2,%3}, {%4,%5,%6,%7}, {%8,%9}, {%0,%1,%2,%3};\n"
        : "+f"(d[0]), "+f"(d[1]), "+f"(d[2]), "+f"(d[3])
        : "r"(a[0]), "r"(a[1]), "r"(a[2]), "r"(a[3]), "r"(b[0]), "r"(b[1]));
}
__device__ __forceinline__ void ldsm4(uint32_t* r, uint32_t addr) {
    asm volatile("ldmatrix.sync.aligned.m8n8.x4.shared.b16 {%0,%1,%2,%3}, [%4];"
                 : "=r"(r[0]), "=r"(r[1]), "=r"(r[2]), "=r"(r[3]) : "r"(addr));
}
__device__ __forceinline__ void ldsm4t(uint32_t* r, uint32_t addr) {
    asm volatile("ldmatrix.sync.aligned.m8n8.x4.trans.shared.b16 {%0,%1,%2,%3}, [%4];"
                 : "=r"(r[0]), "=r"(r[1]), "=r"(r[2]), "=r"(r[3]) : "r"(addr));
}
#define CP_ASYNC16(dst32, src) \
    asm volatile("cp.async.cg.shared.global [%0], [%1], 16;\n" :: "r"(dst32), "l"(src))
#define CP_COMMIT() asm volatile("cp.async.commit_group;\n")
#define CP_WAIT0()  asm volatile("cp.async.wait_group 0;\n")
#define CP_WAIT1()  asm volatile("cp.async.wait_group 1;\n")

__device__ __forceinline__ uint32_t packh2(float a, float b) {
    __half2 h = __floats2half2_rn(a, b);
    return *reinterpret_cast<uint32_t*>(&h);
}

// ---------------------------------------------------------------------------
// f32 -> f16 conversion (vectorized)
// ---------------------------------------------------------------------------
__global__ void f2h_kernel(const float* __restrict__ in, __half* __restrict__ out, int n2) {
    int i = blockIdx.x * blockDim.x + threadIdx.x;
    if (i < n2) {
        float2 v = ((const float2*)in)[i];
        ((__half2*)out)[i] = __floats2half2_rn(v.x, v.y);
    }
}

// ---------------------------------------------------------------------------
// RoPE table in double precision (fast-math-proof; angles up to ~2047 rad)
// ---------------------------------------------------------------------------
__global__ void rope_table_kernel() {
    int i = blockIdx.x * blockDim.x + threadIdx.x;
    if (i >= S_LEN * 64) return;
    int s = i >> 6;
    int d = i & 63;
    double inv_freq = pow(10000.0, -(double)d / 64.0);
    double a = (double)s * inv_freq;
    g_cos[i] = (float)cos(a);
    g_sin[i] = (float)sin(a);
}

// RoPE applied in-place on the half qkv buffer (Q heads 0-15, K heads 16-17).
__global__ void rope_apply_h(__half* __restrict__ q) {
    int i = blockIdx.x * blockDim.x + threadIdx.x;
    const int total = ROWS * 18 * 32;
    if (i >= total) return;
    int dp   = (i & 31) * 2;
    int rest = i >> 5;
    int hh   = rest % 18;
    int row  = rest / 18;
    int s    = row & (S_LEN - 1);
    size_t base = (size_t)row * QKV_COLS +
                  (hh < 16 ? (size_t)hh * HD : (size_t)(NH * HD) + (size_t)(hh - 16) * HD);
    float2 c  = *(const float2*)&g_cos[(s << 6) + dp];
    float2 sn = *(const float2*)&g_sin[(s << 6) + dp];
    float2 x1 = __half22float2(*(__half2*)&q[base + dp]);
    float2 x2 = __half22float2(*(__half2*)&q[base + dp + 64]);
    *(__half2*)&q[base + dp]      = __floats2half2_rn(x1.x * c.x - x2.x * sn.x,
                                                      x1.y * c.y - x2.y * sn.y);
    *(__half2*)&q[base + dp + 64] = __floats2half2_rn(x1.x * sn.x + x2.x * c.x,
                                                      x1.y * sn.y + x2.y * c.y);
}

// ---------------------------------------------------------------------------
// FP16 GEMM (f32 accumulate), 3-stage cp.async pipeline.
// C[M,N] = A[M,K] @ B[K,N], both half row-major.
// BM=BN=128, BK=32, 256 threads = 8 warps (4x2), warp tile 32x64.
// ---------------------------------------------------------------------------
#define GA_ST (128 * 40 * 2)   // A stage bytes (stride 40 halves)
#define GB_ST (32 * 136 * 2)   // B stage bytes (stride 136 halves)
#define GEMM_SMEM_BYTES (3 * (GA_ST + GB_ST))

template <bool OUTHALF>
__global__ __launch_bounds__(256, 2)
void gemm_f16(const __half* __restrict__ A, const __half* __restrict__ B,
              void* __restrict__ Cv, int M, int N, int K) {
    extern __shared__ __align__(16) char gsm[];
    const uint32_t sbase = (uint32_t)__cvta_generic_to_shared(gsm);

    const int tid = threadIdx.x, lane = tid & 31, warp = tid >> 5;
    const int wm = warp >> 1, wn = warp & 1, g4 = lane >> 2, t4 = lane & 3;

    const __half* Ab = A + (size_t)blockIdx.y * 128 * K;
    const __half* Bb = B + (size_t)blockIdx.x * 128;

    // ldmatrix lane geometry
    const int lsub  = lane >> 3;
    const int arow  = ((lsub & 1) << 3) + (lane & 7);
    const int acolh = (lsub >> 1) << 3;
    const int vrow  = lane & 15;
    const int vcolh = (lane >> 4) << 3;

    const int aR = tid >> 2, aC = tid & 3;        // A: row, 16B chunk
    const int bR = tid >> 4, bC = tid & 15;       // B: row, 16B chunk

    auto issue = [&](int t, int st) {
        uint32_t sA = sbase + st * (GA_ST + GB_ST);
        uint32_t sB = sA + GA_ST;
#pragma unroll
        for (int i = 0; i < 2; i++) {
            int r = aR + 64 * i;
            CP_ASYNC16(sA + r * 80 + aC * 16, Ab + (size_t)r * K + t * 32 + aC * 8);
        }
#pragma unroll
        for (int i = 0; i < 2; i++) {
            int r = bR + 16 * i;
            CP_ASYNC16(sB + r * 272 + bC * 16, Bb + (size_t)(t * 32 + r) * N + bC * 8);
        }
        CP_COMMIT();
    };

    float acc[2][8][4];
#pragma unroll
    for (int mt = 0; mt < 2; mt++)
#pragma unroll
        for (int nt = 0; nt < 8; nt++)
#pragma unroll
            for (int r = 0; r < 4; r++) acc[mt][nt][r] = 0.0f;

    const int T = K / 32;
    issue(0, 0);
    issue(1, 1);

    for (int t = 0; t < T; t++) {
        const int cur = t % 3;
        CP_WAIT1();
        __syncthreads();
        if (t + 2 < T) issue(t + 2, (t + 2) % 3);

        const uint32_t sA = sbase + cur * (GA_ST + GB_ST);
        const uint32_t sB = sA + GA_ST;
#pragma unroll
        for (int ks = 0; ks < 2; ks++) {
            uint32_t af[2][4];
#pragma unroll
            for (int mt = 0; mt < 2; mt++)
                ldsm4(af[mt], sA + (wm * 32 + mt * 16 + arow) * 80 + (ks * 16 + acolh) * 2);
            uint32_t bf[8][2];
#pragma unroll
            for (int tt = 0; tt < 4; tt++) {
                uint32_t v[4];
                ldsm4t(v, sB + (ks * 16 + vrow) * 272 + (wn * 64 + tt * 16 + vcolh) * 2);
                bf[2 * tt][0] = v[0]; bf[2 * tt][1] = v[1];
                bf[2 * tt + 1][0] = v[2]; bf[2 * tt + 1][1] = v[3];
            }
#pragma unroll
            for (int mt = 0; mt < 2; mt++)
#pragma unroll
                for (int nt = 0; nt < 8; nt++)
                    mma_f16(acc[mt][nt], af[mt], bf[nt]);
        }
        __syncthreads();
    }

#pragma unroll
    for (int mt = 0; mt < 2; mt++) {
        int r0 = blockIdx.y * 128 + wm * 32 + mt * 16 + g4;
#pragma unroll
        for (int nt = 0; nt < 8; nt++) {
            int c = blockIdx.x * 128 + wn * 64 + nt * 8 + 2 * t4;
            if (OUTHALF) {
                __half* C = (__half*)Cv;
                *(__half2*)(C + (size_t)r0 * N + c)       = __floats2half2_rn(acc[mt][nt][0], acc[mt][nt][1]);
                *(__half2*)(C + (size_t)(r0 + 8) * N + c) = __floats2half2_rn(acc[mt][nt][2], acc[mt][nt][3]);
            } else {
                float* C = (float*)Cv;
                *(float2*)(C + (size_t)r0 * N + c)       = make_float2(acc[mt][nt][0], acc[mt][nt][1]);
                *(float2*)(C + (size_t)(r0 + 8) * N + c) = make_float2(acc[mt][nt][2], acc[mt][nt][3]);
            }
        }
    }
}

// ---------------------------------------------------------------------------
// FP16 flash attention, warp-owns-full-row layout.
// BM=128 Q rows, BN=64 keys, 256 threads = 8 warps; warp tile = 16 rows x 64 keys.
// Row softmax entirely in quad shuffles; P stays in registers (S-frag == PV A-frag).
// One __syncthreads per KV tile (stage management only).
// ---------------------------------------------------------------------------
#define AQ_B 272                        // 136 halves per row
#define AOFF_Q  0
#define AOFF_K  34816                   // 128*272
#define AKV_ST  17408                   // 64*272
#define AOFF_V  (AOFF_K + 2 * AKV_ST)
#define ATTN_SMEM_BYTES (AOFF_V + 2 * AKV_ST)   // 104448

__global__ __launch_bounds__(256, 1)
void attn_kernel(const __half* __restrict__ qkv, __half* __restrict__ out) {
    extern __shared__ __align__(16) char smraw[];
    const uint32_t sbase = (uint32_t)__cvta_generic_to_shared(smraw);

    const int qb = (int)gridDim.x - 1 - (int)blockIdx.x;  // longest first
    const int h  = blockIdx.y;
    const int b  = blockIdx.z;
    const int g  = h / REP;

    const int tid = threadIdx.x, lane = tid & 31, warp = tid >> 5;
    const int g4 = lane >> 2, t4 = lane & 3;

    const size_t rs = QKV_COLS;
    const __half* qbase = qkv + ((size_t)b * S_LEN + (size_t)qb * 128) * rs + (size_t)h * HD;
    const __half* kbase = qkv + (size_t)b * S_LEN * rs + (size_t)(NH * HD) + (size_t)g * HD;
    const __half* vbase = kbase + (size_t)(NKV * HD);

    // ldmatrix lane geometry
    const int lsub  = lane >> 3;
    const int arow  = ((lsub & 1) << 3) + (lane & 7);
    const int acolh = (lsub >> 1) << 3;
    const int krow  = ((lane >> 4) << 3) + (lane & 7);
    const int kcolh = ((lane >> 3) & 1) << 3;
    const int vrow  = lane & 15;
    const int vcolh = (lane >> 4) << 3;

    // prologue: Q (128 rows) + K/V tile 0 into stage 0
#pragma unroll
    for (int i = 0; i < 8; i++) {
        int idx = tid + 256 * i;
        int r = idx >> 4, ch = idx & 15;
        CP_ASYNC16(sbase + AOFF_Q + r * AQ_B + ch * 16, qbase + (size_t)r * rs + ch * 8);
    }
#pragma unroll
    for (int i = 0; i < 4; i++) {
        int idx = tid + 256 * i;
        int r = idx >> 4, ch = idx & 15;
        CP_ASYNC16(sbase + AOFF_K + r * AQ_B + ch * 16, kbase + (size_t)r * rs + ch * 8);
        CP_ASYNC16(sbase + AOFF_V + r * AQ_B + ch * 16, vbase + (size_t)r * rs + ch * 8);
    }
    CP_COMMIT();

    float m0 = -1e30f, m1 = -1e30f, l0 = 0.0f, l1 = 0.0f;
    float o[16][4];
#pragma unroll
    for (int nt = 0; nt < 16; nt++)
#pragma unroll
        for (int r = 0; r < 4; r++) o[nt][r] = 0.0f;

    const uint32_t aQ = sbase + AOFF_Q + (warp * 16 + arow) * AQ_B + acolh * 2;
    const int grow0 = qb * 128 + warp * 16 + g4;   // global rows (g4, g4+8)
    const int ktmax = 2 * qb + 1;

    for (int kt = 0; kt <= ktmax; kt++) {
        const int cur = kt & 1;
        CP_WAIT0();
        __syncthreads();   // stage cur ready; all warps done reading stage cur^1

        if (kt < ktmax) {
            const __half* kb = kbase + (size_t)(kt + 1) * 64 * rs;
            const __half* vb = vbase + (size_t)(kt + 1) * 64 * rs;
            const uint32_t kd = sbase + AOFF_K + (cur ^ 1) * AKV_ST;
            const uint32_t vd = sbase + AOFF_V + (cur ^ 1) * AKV_ST;
#pragma unroll
            for (int i = 0; i < 4; i++) {
                int idx = tid + 256 * i;
                int r = idx >> 4, ch = idx & 15;
                CP_ASYNC16(kd + r * AQ_B + ch * 16, kb + (size_t)r * rs + ch * 8);
                CP_ASYNC16(vd + r * AQ_B + ch * 16, vb + (size_t)r * rs + ch * 8);
            }
            CP_COMMIT();
        }

        const uint32_t bK = sbase + AOFF_K + cur * AKV_ST + krow * AQ_B + kcolh * 2;
        const uint32_t bV = sbase + AOFF_V + cur * AKV_ST + vrow * AQ_B + vcolh * 2;

        // ---- S = Q K^T : 16 rows x 64 keys per warp ----
        float sfr[8][4];
#pragma unroll
        for (int nt = 0; nt < 8; nt++)
#pragma unroll
            for (int r = 0; r < 4; r++) sfr[nt][r] = 0.0f;

#pragma unroll
        for (int ks = 0; ks < 8; ks++) {
            uint32_t af[4];
            ldsm4(af, aQ + ks * 32);
#pragma unroll
            for (int nt2 = 0; nt2 < 4; nt2++) {
                uint32_t bb[4];
                ldsm4(bb, bK + nt2 * 16 * AQ_B + ks * 32);
                mma_f16(sfr[2 * nt2],     af, &bb[0]);
                mma_f16(sfr[2 * nt2 + 1], af, &bb[2]);
            }
        }

        // ---- softcap (exact, via expf) + causal + row softmax (quad-only) ----
        const bool diag = (kt >= 2 * qb);
        float mx0 = -1e30f, mx1 = -1e30f;
#pragma unroll
        for (int nt = 0; nt < 8; nt++) {
            int gk = kt * 64 + nt * 8 + 2 * t4;
#pragma unroll
            for (int j = 0; j < 2; j++) {
                // 30*tanh(y) = 30*(1-u)/(1+u), u = exp(-2y)
                float y0 = sfr[nt][j] * (SCALE_F / SOFTCAP_F);
                float y1 = sfr[nt][2 + j] * (SCALE_F / SOFTCAP_F);
                float u0 = __expf(-2.0f * y0);
                float u1 = __expf(-2.0f * y1);
                float v0 = SOFTCAP_F * __fdividef(1.0f - u0, 1.0f + u0);
                float v1 = SOFTCAP_F * __fdividef(1.0f - u1, 1.0f + u1);
                if (diag && (gk + j) > grow0)     v0 = -1e30f;
                if (diag && (gk + j) > grow0 + 8) v1 = -1e30f;
                sfr[nt][j] = v0; sfr[nt][2 + j] = v1;
                mx0 = fmaxf(mx0, v0); mx1 = fmaxf(mx1, v1);
            }
        }
        mx0 = fmaxf(mx0, __shfl_xor_sync(0xffffffffu, mx0, 1));
        mx0 = fmaxf(mx0, __shfl_xor_sync(0xffffffffu, mx0, 2));
        mx1 = fmaxf(mx1, __shfl_xor_sync(0xffffffffu, mx1, 1));
        mx1 = fmaxf(mx1, __shfl_xor_sync(0xffffffffu, mx1, 2));

        float mn0 = fmaxf(m0, mx0);
        float mn1 = fmaxf(m1, mx1);
        float corr0 = __expf(m0 - mn0);
        float corr1 = __expf(m1 - mn1);
        m0 = mn0; m1 = mn1;

        float sum0 = 0.0f, sum1 = 0.0f;
#pragma unroll
        for (int nt = 0; nt < 8; nt++) {
            float p00 = __expf(sfr[nt][0] - mn0);
            float p01 = __expf(sfr[nt][1] - mn0);
            float p10 = __expf(sfr[nt][2] - mn1);
            float p11 = __expf(sfr[nt][3] - mn1);
            sum0 += p00 + p01; sum1 += p10 + p11;
            sfr[nt][0] = p00; sfr[nt][1] = p01;
            sfr[nt][2] = p10; sfr[nt][3] = p11;
        }
        l0 = l0 * corr0 + sum0;
        l1 = l1 * corr1 + sum1;

#pragma unroll
        for (int nt = 0; nt < 16; nt++) {
            o[nt][0] *= corr0; o[nt][1] *= corr0;
            o[nt][2] *= corr1; o[nt][3] *= corr1;
        }

        // ---- O += P @ V : P straight from registers (S-frag == A-frag) ----
#pragma unroll
        for (int kk = 0; kk < 4; kk++) {
            uint32_t af[4];
            af[0] = packh2(sfr[2 * kk][0],     sfr[2 * kk][1]);
            af[1] = packh2(sfr[2 * kk][2],     sfr[2 * kk][3]);
            af[2] = packh2(sfr[2 * kk + 1][0], sfr[2 * kk + 1][1]);
            af[3] = packh2(sfr[2 * kk + 1][2], sfr[2 * kk + 1][3]);
#pragma unroll
            for (int tt = 0; tt < 8; tt++) {
                uint32_t v[4];
                ldsm4t(v, bV + kk * 16 * AQ_B + tt * 32);
                mma_f16(o[2 * tt],     af, &v[0]);
                mma_f16(o[2 * tt + 1], af, &v[2]);
            }
        }
    }

    // finalize: quad-reduce l, normalize, write
    l0 += __shfl_xor_sync(0xffffffffu, l0, 1);
    l0 += __shfl_xor_sync(0xffffffffu, l0, 2);
    l1 += __shfl_xor_sync(0xffffffffu, l1, 1);
    l1 += __shfl_xor_sync(0xffffffffu, l1, 2);
    float inv0 = 1.0f / l0;
    float inv1 = 1.0f / l1;

    size_t gr0 = (size_t)b * S_LEN + grow0;
#pragma unroll
    for (int nt = 0; nt < 16; nt++) {
        int c = h * HD + nt * 8 + 2 * t4;
        *(__half2*)(out + gr0 * HIDDEN + c)       = __floats2half2_rn(o[nt][0] * inv0, o[nt][1] * inv0);
        *(__half2*)(out + (gr0 + 8) * HIDDEN + c) = __floats2half2_rn(o[nt][2] * inv1, o[nt][3] * inv1);
    }
}

// ---------------------------------------------------------------------------
// Launch
// ---------------------------------------------------------------------------
extern "C" void kernel_launch(void* const* d_in, const int* in_sizes, int n_in,
                              void* d_out, int out_size) {
    (void)in_sizes; (void)n_in; (void)out_size;
    const float* hidden = (const float*)d_in[0];
    const float* Wqkv   = (const float*)d_in[1];
    const float* Wo     = (const float*)d_in[2];
    float* out = (float*)d_out;

    void* p;
    cudaGetSymbolAddress(&p, g_hh);    __half* hh    = (__half*)p;
    cudaGetSymbolAddress(&p, g_wqkvh); __half* wqkvh = (__half*)p;
    cudaGetSymbolAddress(&p, g_woh);   __half* woh   = (__half*)p;
    cudaGetSymbolAddress(&p, g_qkvh);  __half* qkvh  = (__half*)p;
    cudaGetSymbolAddress(&p, g_attnh); __half* attnh = (__half*)p;

    cudaFuncSetAttribute(attn_kernel, cudaFuncAttributeMaxDynamicSharedMemorySize,
                         ATTN_SMEM_BYTES);
    cudaFuncSetAttribute(gemm_f16<true>, cudaFuncAttributeMaxDynamicSharedMemorySize,
                         GEMM_SMEM_BYTES);
    cudaFuncSetAttribute(gemm_f16<false>, cudaFuncAttributeMaxDynamicSharedMemorySize,
                         GEMM_SMEM_BYTES);

    rope_table_kernel<<<(S_LEN * 64 + 255) / 256, 256>>>();

    // convert inputs to half
    {
        int n2;
        n2 = ROWS * HIDDEN / 2;
        f2h_kernel<<<(n2 + 255) / 256, 256>>>(hidden, hh, n2);
        n2 = HIDDEN * QKV_COLS / 2;
        f2h_kernel<<<(n2 + 255) / 256, 256>>>(Wqkv, wqkvh, n2);
        n2 = HIDDEN * HIDDEN / 2;
        f2h_kernel<<<(n2 + 255) / 256, 256>>>(Wo, woh, n2);
    }

    // 1) QKV projection (half output)
    gemm_f16<true><<<dim3(QKV_COLS / 128, ROWS / 128), 256, GEMM_SMEM_BYTES>>>(
        hh, wqkvh, qkvh, ROWS, QKV_COLS, HIDDEN);
    // 2) RoPE on Q + K in place (half)
    {
        int total = ROWS * 18 * 32;
        rope_apply_h<<<(total + 255) / 256, 256>>>(qkvh);
    }
    // 3) Flash attention (warp-row layout, register P)
    attn_kernel<<<dim3(S_LEN / 128, NH, BATCH), 256, ATTN_SMEM_BYTES>>>(qkvh, attnh);

    // 4) Output projection (float output)
    gemm_f16<false><<<dim3(HIDDEN / 128, ROWS / 128), 256, GEMM_SMEM_BYTES>>>(
        attnh, woh, out, ROWS, HIDDEN, HIDDEN);
}